// round 5
// baseline (speedup 1.0000x reference)
#include <cuda_runtime.h>
#include <math_constants.h>

#define D_MODEL 768
#define NHEAD   12
#define DK      64
#define MAXM    8192   // B*S = 2*4096

// ---- scratch (no cudaMalloc allowed) ----
__device__ float g_q [MAXM * D_MODEL];
__device__ float g_k [MAXM * D_MODEL];
__device__ float g_v [MAXM * D_MODEL];
__device__ float g_ao[MAXM * D_MODEL];

// ---- tf32 helpers ----
__device__ __forceinline__ float f2tff(float x) {
    unsigned u; asm("cvt.rna.tf32.f32 %0, %1;" : "=r"(u) : "f"(x));
    return __uint_as_float(u);
}

__device__ __forceinline__ void mma_tf32(
    float& c0, float& c1, float& c2, float& c3,
    float a0, float a1, float a2, float a3,
    float b0, float b1)
{
    asm volatile(
        "mma.sync.aligned.m16n8k8.row.col.f32.tf32.tf32.f32 "
        "{%0,%1,%2,%3},{%4,%5,%6,%7},{%8,%9},{%0,%1,%2,%3};"
        : "+f"(c0), "+f"(c1), "+f"(c2), "+f"(c3)
        : "r"(__float_as_uint(a0)), "r"(__float_as_uint(a1)),
          "r"(__float_as_uint(a2)), "r"(__float_as_uint(a3)),
          "r"(__float_as_uint(b0)), "r"(__float_as_uint(b1)));
}

// Layouts:
//  A-pack (16-row m-tile, 8-col k-block): blk*132 + 16g + 4t + (hi + 2h)
//    -> one LDS.128 per lane = {a0,a1,a2,a3}
//  B-pair-pack (8-row n-tile, 16-col k-slab = 2 k-blocks): blk*132 + 16g + 4t + si
//    component si -> element k = 16p + 4*si + t  -> one LDS.128 feeds 2 k-steps
//  B-single (stride-68 blocks): LDS.64 = {b0, b1}

// ============================================================================
// NT GEMM via tf32 mma: C[m][n] = bias[n] + sum_k A[m][k] * W[n][k]
// Tile 128x64x32, 256 threads (8 warps, 4m x 2n), warp tile 32x32.
// W uses paired k-slabs (one LDS.128 feeds two k-steps).
// ============================================================================
__global__ __launch_bounds__(256) void gemm_nt_tc(
    const float* __restrict__ A, const float* __restrict__ W,
    const float* __restrict__ bias, float* __restrict__ C,
    int M, int N, int K)
{
    __shared__ float Af[32 * 132];   // blk = rt*4 + kk   (rt 0..7, kk 0..3)
    __shared__ float Wf[16 * 132];   // blk = nt*2 + p    (nt 0..7, p 0..1)

    const int tid  = threadIdx.x;
    const int lane = tid & 31, warp = tid >> 5;
    const int g = lane >> 2, t = lane & 3;
    const int rm = warp >> 1;
    const int wn = warp & 1;
    const int bm = blockIdx.y * 128, bn = blockIdx.x * 64;

    float c[2][4][4] = {};

    for (int k0 = 0; k0 < K; k0 += 32) {
        // stage A (128x32) A-packed
#pragma unroll
        for (int p = 0; p < 4; p++) {
            int fl = p * 256 + tid;
            int r = fl >> 3, cc = (fl & 7) << 2;
            float4 v = *(const float4*)(A + (size_t)(bm + r) * K + k0 + cc);
            int dst = ((r>>4)*4 + (cc>>3))*132 + 16*(r&7) + ((r>>3)&1) + 2*((cc>>2)&1);
            Af[dst     ] = f2tff(v.x);
            Af[dst +  4] = f2tff(v.y);
            Af[dst +  8] = f2tff(v.z);
            Af[dst + 12] = f2tff(v.w);
        }
        // stage W (64x32) pair-packed  (FIX: full 2-pass coverage of 64 rows)
#pragma unroll
        for (int p = 0; p < 2; p++) {
            int fl = p * 256 + tid;
            int r = fl >> 3, cc = (fl & 7) << 2;
            float4 v = *(const float4*)(W + (size_t)(bn + r) * K + k0 + cc);
            int dst = ((r>>3)*2 + (cc>>4))*132 + 16*(r&7) + ((cc>>2)&3);
            Wf[dst     ] = f2tff(v.x);
            Wf[dst +  4] = f2tff(v.y);
            Wf[dst +  8] = f2tff(v.z);
            Wf[dst + 12] = f2tff(v.w);
        }
        __syncthreads();

#pragma unroll
        for (int p = 0; p < 2; p++) {
            float4 aE[2], aO[2];
#pragma unroll
            for (int mt = 0; mt < 2; mt++) {
                aE[mt] = *(const float4*)&Af[((rm*2 + mt)*4 + 2*p    )*132 + lane*4];
                aO[mt] = *(const float4*)&Af[((rm*2 + mt)*4 + 2*p + 1)*132 + lane*4];
            }
#pragma unroll
            for (int nt = 0; nt < 4; nt++) {
                float4 b4 = *(const float4*)&Wf[((wn*4 + nt)*2 + p)*132 + lane*4];
#pragma unroll
                for (int mt = 0; mt < 2; mt++) {
                    mma_tf32(c[mt][nt][0], c[mt][nt][1], c[mt][nt][2], c[mt][nt][3],
                             aE[mt].x, aE[mt].y, aE[mt].z, aE[mt].w, b4.x, b4.y);
                    mma_tf32(c[mt][nt][0], c[mt][nt][1], c[mt][nt][2], c[mt][nt][3],
                             aO[mt].x, aO[mt].y, aO[mt].z, aO[mt].w, b4.z, b4.w);
                }
            }
        }
        __syncthreads();
    }

#pragma unroll
    for (int mt = 0; mt < 2; mt++) {
#pragma unroll
        for (int nt = 0; nt < 4; nt++) {
            int row = bm + rm*32 + mt*16 + g;
            int col = bn + wn*32 + nt*8 + 2*t;
            float2 b2 = *(const float2*)(bias + col);
            *(float2*)(C + (size_t)row * N + col) =
                make_float2(c[mt][nt][0] + b2.x, c[mt][nt][1] + b2.y);
            *(float2*)(C + (size_t)(row + 8) * N + col) =
                make_float2(c[mt][nt][2] + b2.x, c[mt][nt][3] + b2.y);
        }
    }
}

// ============================================================================
// Flash attention, tf32 mma. 256 threads, 8 warps x 16 q-rows, CTA = 128 rows.
// KV tile = 64 keys. K pair-packed (LDS.128 -> 2 k-steps), V/Ps B-single.
// ============================================================================
// smem floats: Qf 8448 | Kf 32*132=4224 | Vf 64*68=4352 | Ps 128*68=8704
#define OFF_KF 8448
#define OFF_VF 12672
#define OFF_PS 17024
#define SMEM_FLASH (25728 * 4)

__global__ __launch_bounds__(256, 2) void flash_tc(
    const float* __restrict__ Qp, const float* __restrict__ Kp,
    const float* __restrict__ Vp, float* __restrict__ Op, int S)
{
    extern __shared__ float sm[];
    float* Qf = sm;                 // blk = (rt*8 + kk)*132, rt=warp 0..7, kk 0..7
    float* Kf = sm + OFF_KF;        // blk = (nt*4 + p)*132,  nt 0..7, p 0..3
    float* Vf = sm + OFF_VF;        // blk = (kk*8 + nt)*68   (n=d, k=key)
    float (*Ps)[68] = (float (*)[68])(sm + OFF_PS);

    const int tid  = threadIdx.x;
    const int lane = tid & 31, warp = tid >> 5;
    const int g = lane >> 2, t = lane & 3;
    const int b = blockIdx.y / NHEAD, h = blockIdx.y % NHEAD;
    const int q0 = blockIdx.x * 128;
    const size_t base = ((size_t)b * S) * D_MODEL + (size_t)h * DK;
    const int rbase = warp * 16;

    // stage Q (128x64) A-packed, pre-scaled by 1/8
#pragma unroll
    for (int p = 0; p < 8; p++) {
        int fl = p * 256 + tid;
        int r = fl >> 4, cc = (fl & 15) << 2;
        float4 v = *(const float4*)(Qp + base + (size_t)(q0 + r) * D_MODEL + cc);
        int dst = ((r>>4)*8 + (cc>>3))*132 + 16*(r&7) + ((r>>3)&1) + 2*((cc>>2)&1);
        Qf[dst     ] = f2tff(v.x * 0.125f);
        Qf[dst +  4] = f2tff(v.y * 0.125f);
        Qf[dst +  8] = f2tff(v.z * 0.125f);
        Qf[dst + 12] = f2tff(v.w * 0.125f);
    }

    float o[8][4] = {};
    float m0 = -CUDART_INF_F, m1 = -CUDART_INF_F, l0 = 0.f, l1 = 0.f;
    __syncthreads();

    for (int kv0 = 0; kv0 < S; kv0 += 64) {
        // stage K (64 keys x 64 d) pair-packed: n=key, k=d
#pragma unroll
        for (int p = 0; p < 4; p++) {
            int fl = p * 256 + tid;
            int r = fl >> 4, cc = (fl & 15) << 2;
            float4 v = *(const float4*)(Kp + base + (size_t)(kv0 + r) * D_MODEL + cc);
            int dst = ((r>>3)*4 + (cc>>4))*132 + 16*(r&7) + ((cc>>2)&3);
            Kf[dst     ] = f2tff(v.x);
            Kf[dst +  4] = f2tff(v.y);
            Kf[dst +  8] = f2tff(v.z);
            Kf[dst + 12] = f2tff(v.w);
        }
        // stage V (64 keys x 64 d) B-single: n=d, k=key
#pragma unroll
        for (int p = 0; p < 4; p++) {
            int fl = p * 256 + tid;
            int r = fl >> 4, cc = (fl & 15) << 2;   // r=key, cc=d group
            float4 v = *(const float4*)(Vp + base + (size_t)(kv0 + r) * D_MODEL + cc);
            int dst = ((r>>3)*8 + (cc>>3))*68 + 8*(cc&7) + 2*(r&3) + ((r>>2)&1);
            Vf[dst     ] = f2tff(v.x);
            Vf[dst +  8] = f2tff(v.y);
            Vf[dst + 16] = f2tff(v.z);
            Vf[dst + 24] = f2tff(v.w);
        }
        __syncthreads();

        // S = Q @ K^T : warp 16x64, k=d=64 as 4 k-pairs
        float s[8][4] = {};
#pragma unroll
        for (int p = 0; p < 4; p++) {
            float4 aE = *(const float4*)&Qf[(warp*8 + 2*p    )*132 + lane*4];
            float4 aO = *(const float4*)&Qf[(warp*8 + 2*p + 1)*132 + lane*4];
#pragma unroll
            for (int nt = 0; nt < 8; nt++) {
                float4 b4 = *(const float4*)&Kf[(nt*4 + p)*132 + lane*4];
                mma_tf32(s[nt][0], s[nt][1], s[nt][2], s[nt][3],
                         aE.x, aE.y, aE.z, aE.w, b4.x, b4.y);
                mma_tf32(s[nt][0], s[nt][1], s[nt][2], s[nt][3],
                         aO.x, aO.y, aO.z, aO.w, b4.z, b4.w);
            }
        }

        // online softmax (4-lane quad owns a row) + stage P
        {
            float mx0 = -CUDART_INF_F, mx1 = -CUDART_INF_F;
#pragma unroll
            for (int nt = 0; nt < 8; nt++) {
                mx0 = fmaxf(mx0, fmaxf(s[nt][0], s[nt][1]));
                mx1 = fmaxf(mx1, fmaxf(s[nt][2], s[nt][3]));
            }
#pragma unroll
            for (int off = 2; off >= 1; off >>= 1) {
                mx0 = fmaxf(mx0, __shfl_xor_sync(0xffffffffu, mx0, off));
                mx1 = fmaxf(mx1, __shfl_xor_sync(0xffffffffu, mx1, off));
            }
            float mn0 = fmaxf(m0, mx0), mn1 = fmaxf(m1, mx1);
            float al0 = __expf(m0 - mn0), al1 = __expf(m1 - mn1);
            m0 = mn0; m1 = mn1;

            float rs0 = 0.f, rs1 = 0.f;
#pragma unroll
            for (int nt = 0; nt < 8; nt++) {
                float p0 = __expf(s[nt][0] - mn0);
                float p1 = __expf(s[nt][1] - mn0);
                float p2 = __expf(s[nt][2] - mn1);
                float p3 = __expf(s[nt][3] - mn1);
                rs0 += p0 + p1; rs1 += p2 + p3;
                int col = nt*8 + 2*t;
                *(float2*)&Ps[rbase + g    ][col] = make_float2(f2tff(p0), f2tff(p1));
                *(float2*)&Ps[rbase + g + 8][col] = make_float2(f2tff(p2), f2tff(p3));
            }
#pragma unroll
            for (int off = 2; off >= 1; off >>= 1) {
                rs0 += __shfl_xor_sync(0xffffffffu, rs0, off);
                rs1 += __shfl_xor_sync(0xffffffffu, rs1, off);
            }
            l0 = l0 * al0 + rs0;
            l1 = l1 * al1 + rs1;
#pragma unroll
            for (int nt = 0; nt < 8; nt++) {
                o[nt][0] *= al0; o[nt][1] *= al0;
                o[nt][2] *= al1; o[nt][3] *= al1;
            }
        }
        __syncwarp();   // Ps rows are warp-private

        // O += P @ V : k=key=64
#pragma unroll
        for (int kk = 0; kk < 8; kk++) {
            const int kb = kk * 8;
            float a0 = Ps[rbase + g    ][kb + t    ];
            float a1 = Ps[rbase + g + 8][kb + t    ];
            float a2 = Ps[rbase + g    ][kb + t + 4];
            float a3 = Ps[rbase + g + 8][kb + t + 4];
#pragma unroll
            for (int nt = 0; nt < 8; nt++) {
                float2 b2 = *(const float2*)&Vf[(kk*8 + nt)*68 + lane*2];
                mma_tf32(o[nt][0], o[nt][1], o[nt][2], o[nt][3],
                         a0, a1, a2, a3, b2.x, b2.y);
            }
        }
        __syncthreads();   // Kf/Vf reuse next iter
    }

    // epilogue: normalize, write (B,S,H*DK) layout
    float inv0 = 1.f / l0, inv1 = 1.f / l1;
    int row = q0 + rbase + g;
#pragma unroll
    for (int nt = 0; nt < 8; nt++) {
        int col = nt*8 + 2*t;
        *(float2*)(Op + base + (size_t)row * D_MODEL + col) =
            make_float2(o[nt][0]*inv0, o[nt][1]*inv0);
        *(float2*)(Op + base + (size_t)(row + 8) * D_MODEL + col) =
            make_float2(o[nt][2]*inv1, o[nt][3]*inv1);
    }
}

// ============================================================================
extern "C" void kernel_launch(void* const* d_in, const int* in_sizes, int n_in,
                              void* d_out, int out_size)
{
    const float* Q  = (const float*)d_in[0];
    const float* K  = (const float*)d_in[1];
    const float* V  = (const float*)d_in[2];
    const float* Wq = (const float*)d_in[3];
    const float* bq = (const float*)d_in[4];
    const float* Wk = (const float*)d_in[5];
    const float* bk = (const float*)d_in[6];
    const float* Wv = (const float*)d_in[7];
    const float* bv = (const float*)d_in[8];
    const float* Wo = (const float*)d_in[9];
    const float* bo = (const float*)d_in[10];
    float* out = (float*)d_out;

    const int M = in_sizes[0] / D_MODEL;   // B*S
    const int S = 4096;
    const int B = M / S;

    float *gq, *gk, *gv, *go;
    cudaGetSymbolAddress((void**)&gq, g_q);
    cudaGetSymbolAddress((void**)&gk, g_k);
    cudaGetSymbolAddress((void**)&gv, g_v);
    cudaGetSymbolAddress((void**)&go, g_ao);

    cudaFuncSetAttribute(flash_tc, cudaFuncAttributeMaxDynamicSharedMemorySize, SMEM_FLASH);

    dim3 tb(256);
    dim3 gg(D_MODEL / 64, M / 128);
    gemm_nt_tc<<<gg, tb>>>(Q, Wq, bq, gq, M, D_MODEL, D_MODEL);
    gemm_nt_tc<<<gg, tb>>>(K, Wk, bk, gk, M, D_MODEL, D_MODEL);
    gemm_nt_tc<<<gg, tb>>>(V, Wv, bv, gv, M, D_MODEL, D_MODEL);

    flash_tc<<<dim3(S / 128, B * NHEAD), dim3(256), SMEM_FLASH>>>(gq, gk, gv, go, S);

    gemm_nt_tc<<<gg, tb>>>(go, Wo, bo, out, M, D_MODEL, D_MODEL);
}

// round 7
// speedup vs baseline: 1.2736x; 1.2736x over previous
#include <cuda_runtime.h>
#include <math_constants.h>
#include <cstdint>

#define D_MODEL 768
#define NHEAD   12
#define DK      64
#define MAXM    8192   // B*S = 2*4096

// ---- scratch (no cudaMalloc allowed) ----
__device__ float g_q [MAXM * D_MODEL];
__device__ float g_k [MAXM * D_MODEL];
__device__ float g_v [MAXM * D_MODEL];
__device__ float g_ao[MAXM * D_MODEL];

// ---- tf32 helpers ----
__device__ __forceinline__ float f2tff(float x) {
    unsigned u; asm("cvt.rna.tf32.f32 %0, %1;" : "=r"(u) : "f"(x));
    return __uint_as_float(u);
}

__device__ __forceinline__ void mma_tf32(
    float& c0, float& c1, float& c2, float& c3,
    float a0, float a1, float a2, float a3,
    float b0, float b1)
{
    asm volatile(
        "mma.sync.aligned.m16n8k8.row.col.f32.tf32.tf32.f32 "
        "{%0,%1,%2,%3},{%4,%5,%6,%7},{%8,%9},{%0,%1,%2,%3};"
        : "+f"(c0), "+f"(c1), "+f"(c2), "+f"(c3)
        : "r"(__float_as_uint(a0)), "r"(__float_as_uint(a1)),
          "r"(__float_as_uint(a2)), "r"(__float_as_uint(a3)),
          "r"(__float_as_uint(b0)), "r"(__float_as_uint(b1)));
}

__device__ __forceinline__ uint32_t smem_u32(const void* p) {
    uint32_t a;
    asm("{ .reg .u64 t; cvta.to.shared.u64 t, %1; cvt.u32.u64 %0, t; }"
        : "=r"(a) : "l"(p));
    return a;
}
__device__ __forceinline__ void cpasync4(uint32_t dst, const float* src) {
    asm volatile("cp.async.ca.shared.global [%0], [%1], 4;"
                 :: "r"(dst), "l"(src) : "memory");
}
#define CP_COMMIT() asm volatile("cp.async.commit_group;" ::: "memory")
#define CP_WAIT1()  asm volatile("cp.async.wait_group 1;" ::: "memory")

// ============================================================================
// NT GEMM via tf32 mma (round-3 validated) + epilogue mode:
//   mode 0: C = acc + bias
//   mode 1: C = tf32((acc + bias) * 0.125)   (Q projection: pre-scale+round)
//   mode 2: C = tf32(acc + bias)             (K/V projections: pre-round)
// Tile 128x64x32, 256 threads (8 warps, 4m x 2n), warp tile 32x32.
// ============================================================================
__global__ __launch_bounds__(256) void gemm_nt_tc(
    const float* __restrict__ A, const float* __restrict__ W,
    const float* __restrict__ bias, float* __restrict__ C,
    int M, int N, int K, int mode)
{
    __shared__ float Af[32 * 132];   // blk = rt*4 + kk
    __shared__ float Wf[32 * 66];    // blk = nt*4 + kk

    const int tid  = threadIdx.x;
    const int lane = tid & 31, warp = tid >> 5;
    const int g = lane >> 2, t = lane & 3;
    const int rm = warp >> 1;
    const int wn = warp & 1;
    const int bm = blockIdx.y * 128, bn = blockIdx.x * 64;

    float c[2][4][4] = {};

    for (int k0 = 0; k0 < K; k0 += 32) {
#pragma unroll
        for (int p = 0; p < 4; p++) {
            int fl = p * 256 + tid;
            int r = fl >> 3, cc = (fl & 7) << 2;
            float4 v = *(const float4*)(A + (size_t)(bm + r) * K + k0 + cc);
            int dst = ((r>>4)*4 + (cc>>3))*132 + 16*(r&7) + ((r>>3)&1) + 2*((cc>>2)&1);
            Af[dst     ] = f2tff(v.x);
            Af[dst +  4] = f2tff(v.y);
            Af[dst +  8] = f2tff(v.z);
            Af[dst + 12] = f2tff(v.w);
        }
#pragma unroll
        for (int p = 0; p < 2; p++) {
            int fl = p * 256 + tid;
            int r = fl >> 3, cc = (fl & 7) << 2;
            float4 v = *(const float4*)(W + (size_t)(bn + r) * K + k0 + cc);
            int nt = r >> 3, gg = r & 7;
            int kk = cc >> 3, hh = (cc >> 2) & 1;
            int dst = (nt*4 + kk)*66 + 8*gg + hh;
            Wf[dst    ] = f2tff(v.x);
            Wf[dst + 2] = f2tff(v.y);
            Wf[dst + 4] = f2tff(v.z);
            Wf[dst + 6] = f2tff(v.w);
        }
        __syncthreads();

#pragma unroll
        for (int kk = 0; kk < 4; kk++) {
            float4 a[2];
#pragma unroll
            for (int mt = 0; mt < 2; mt++)
                a[mt] = *(const float4*)&Af[((rm*2 + mt)*4 + kk)*132 + lane*4];
#pragma unroll
            for (int nt = 0; nt < 4; nt++) {
                float2 b2 = *(const float2*)&Wf[((wn*4 + nt)*4 + kk)*66 + lane*2];
#pragma unroll
                for (int mt = 0; mt < 2; mt++)
                    mma_tf32(c[mt][nt][0], c[mt][nt][1], c[mt][nt][2], c[mt][nt][3],
                             a[mt].x, a[mt].y, a[mt].z, a[mt].w, b2.x, b2.y);
            }
        }
        __syncthreads();
    }

#pragma unroll
    for (int mt = 0; mt < 2; mt++) {
#pragma unroll
        for (int nt = 0; nt < 4; nt++) {
            int row = bm + rm*32 + mt*16 + g;
            int col = bn + wn*32 + nt*8 + 2*t;
            float2 b2 = *(const float2*)(bias + col);
            float v0 = c[mt][nt][0] + b2.x, v1 = c[mt][nt][1] + b2.y;
            float v2 = c[mt][nt][2] + b2.x, v3 = c[mt][nt][3] + b2.y;
            if (mode == 1) {
                v0 = f2tff(v0 * 0.125f); v1 = f2tff(v1 * 0.125f);
                v2 = f2tff(v2 * 0.125f); v3 = f2tff(v3 * 0.125f);
            } else if (mode == 2) {
                v0 = f2tff(v0); v1 = f2tff(v1);
                v2 = f2tff(v2); v3 = f2tff(v3);
            }
            *(float2*)(C + (size_t)row * N + col) = make_float2(v0, v1);
            *(float2*)(C + (size_t)(row + 8) * N + col) = make_float2(v2, v3);
        }
    }
}

// ============================================================================
// Flash attention, tf32 mma. 128 threads, warp owns 32 q-rows (2 m-tiles),
// CTA = 128 rows, KV tile = 64 keys, double-buffered via cp.async.
// Inputs pre-converted to tf32 (q also pre-scaled) by projection epilogues.
// P reuses the QK^T C-fragment directly as the PV A-fragment via the key
// permutation perm(k) = 2k mod 8 + (k>>2); V placed at invperm key slots.
// ============================================================================
#define QF_STRIDE 132
#define KF_STRIDE 144
#define VF_STRIDE 76
#define OFF_K0 8448
#define OFF_K1 (OFF_K0 + 32*KF_STRIDE)   // 13056
#define OFF_V0 (OFF_K1 + 32*KF_STRIDE)   // 17664
#define OFF_V1 (OFF_V0 + 64*VF_STRIDE)   // 22528
#define FLASH_FLOATS (OFF_V1 + 64*VF_STRIDE)   // 27392
#define SMEM_FLASH (FLASH_FLOATS * 4)          // 109568 B

__device__ __forceinline__ void stage_K_async(uint32_t kbase_b, const float* Kg, int tid) {
#pragma unroll
    for (int j = 0; j < 32; j++) {
        int fl = j * 128 + tid;
        int r = fl >> 6, c = fl & 63;
        int dst = ((r>>3)*4 + (c>>4))*KF_STRIDE + 16*(r&7) + 4*(c&3) + ((c>>2)&3);
        cpasync4(kbase_b + dst*4, Kg + (size_t)r * D_MODEL + c);
    }
}
__device__ __forceinline__ void stage_V_async(uint32_t vbase_b, const float* Vg, int tid) {
#pragma unroll
    for (int j = 0; j < 32; j++) {
        int fl = j * 128 + tid;
        int r = fl >> 6, c = fl & 63;
        int kk = r >> 3, u = r & 7, tt = u >> 1, hh = u & 1;
        int nt = c >> 3, g0 = c & 7;
        int low = (2*tt + hh) ^ (((g0>>2)&1) << 2) ^ (((nt>>1)&1) << 1);
        int dst = (kk*8 + nt)*VF_STRIDE + 8*g0 + low;
        cpasync4(vbase_b + dst*4, Vg + (size_t)r * D_MODEL + c);
    }
}

__global__ __launch_bounds__(128) void flash_tc(
    const float* __restrict__ Qp, const float* __restrict__ Kp,
    const float* __restrict__ Vp, float* __restrict__ Op, int S)
{
    extern __shared__ float sm[];
    const uint32_t smb = smem_u32(sm);

    const int tid  = threadIdx.x;
    const int lane = tid & 31, warp = tid >> 5;
    const int g = lane >> 2, t = lane & 3;
    const int b = blockIdx.y / NHEAD, h = blockIdx.y % NHEAD;
    const int q0 = blockIdx.x * 128;
    const size_t base = ((size_t)b * S) * D_MODEL + (size_t)h * DK;
    const float* Kg = Kp + base;
    const float* Vg = Vp + base;

    // V fragment-load lane offset (invariant): 8*g0 + (2t ^ 4*sw(g0))
    const int vlaneoff = 8*(lane>>2) + ((2*(lane&3)) ^ (4*((lane>>4)&1)));

    // ---- stage Q (once, sync path; data already tf32 + 0.125-scaled) ----
#pragma unroll
    for (int p = 0; p < 16; p++) {
        int fl = p * 128 + tid;
        int r = fl >> 4, cc = (fl & 15) << 2;
        float4 v = *(const float4*)(Qp + base + (size_t)(q0 + r) * D_MODEL + cc);
        int dst = ((r>>4)*8 + (cc>>3))*QF_STRIDE + 16*(r&7) + ((r>>3)&1) + 2*((cc>>2)&1);
        sm[dst     ] = v.x;
        sm[dst +  4] = v.y;
        sm[dst +  8] = v.z;
        sm[dst + 12] = v.w;
    }

    // ---- prefetch tile 0 ----
    stage_K_async(smb + OFF_K0*4, Kg, tid);
    stage_V_async(smb + OFF_V0*4, Vg, tid);
    CP_COMMIT();

    float o[2][8][4] = {};
    float m_[2][2], l_[2][2];
#pragma unroll
    for (int mt = 0; mt < 2; mt++) {
        m_[mt][0] = m_[mt][1] = -CUDART_INF_F;
        l_[mt][0] = l_[mt][1] = 0.f;
    }

    const int niter = S / 64;
    for (int i = 0; i < niter; i++) {
        // prefetch next tile into the other buffer
        if (i + 1 < niter) {
            uint32_t kb = smb + (((i+1)&1) ? OFF_K1 : OFF_K0)*4;
            uint32_t vb = smb + (((i+1)&1) ? OFF_V1 : OFF_V0)*4;
            stage_K_async(kb, Kg + (size_t)(i+1)*64*D_MODEL, tid);
            stage_V_async(vb, Vg + (size_t)(i+1)*64*D_MODEL, tid);
        }
        CP_COMMIT();
        CP_WAIT1();          // tile i resident
        __syncthreads();

        const float* Kf = sm + ((i&1) ? OFF_K1 : OFF_K0);
        const float* Vf = sm + ((i&1) ? OFF_V1 : OFF_V0);

        // ---- S = Q @ K^T : warp 32x64, k=64 as 4 k-pairs ----
        float s[2][8][4] = {};
#pragma unroll
        for (int p = 0; p < 4; p++) {
            float4 aE[2], aO[2];
#pragma unroll
            for (int mt = 0; mt < 2; mt++) {
                aE[mt] = *(const float4*)&sm[((2*warp + mt)*8 + 2*p    )*QF_STRIDE + lane*4];
                aO[mt] = *(const float4*)&sm[((2*warp + mt)*8 + 2*p + 1)*QF_STRIDE + lane*4];
            }
#pragma unroll
            for (int nt = 0; nt < 8; nt++) {
                float4 b4 = *(const float4*)&Kf[(nt*4 + p)*KF_STRIDE + lane*4];
#pragma unroll
                for (int mt = 0; mt < 2; mt++) {
                    mma_tf32(s[mt][nt][0], s[mt][nt][1], s[mt][nt][2], s[mt][nt][3],
                             aE[mt].x, aE[mt].y, aE[mt].z, aE[mt].w, b4.x, b4.y);
                    mma_tf32(s[mt][nt][0], s[mt][nt][1], s[mt][nt][2], s[mt][nt][3],
                             aO[mt].x, aO[mt].y, aO[mt].z, aO[mt].w, b4.z, b4.w);
                }
            }
        }

        // ---- online softmax (quad owns a row); P stays in s[] registers ----
#pragma unroll
        for (int mt = 0; mt < 2; mt++) {
            float mx0 = -CUDART_INF_F, mx1 = -CUDART_INF_F;
#pragma unroll
            for (int nt = 0; nt < 8; nt++) {
                mx0 = fmaxf(mx0, fmaxf(s[mt][nt][0], s[mt][nt][1]));
                mx1 = fmaxf(mx1, fmaxf(s[mt][nt][2], s[mt][nt][3]));
            }
#pragma unroll
            for (int off = 2; off >= 1; off >>= 1) {
                mx0 = fmaxf(mx0, __shfl_xor_sync(0xffffffffu, mx0, off));
                mx1 = fmaxf(mx1, __shfl_xor_sync(0xffffffffu, mx1, off));
            }
            float mn0 = fmaxf(m_[mt][0], mx0), mn1 = fmaxf(m_[mt][1], mx1);
            float al0 = __expf(m_[mt][0] - mn0), al1 = __expf(m_[mt][1] - mn1);
            m_[mt][0] = mn0; m_[mt][1] = mn1;

            float rs0 = 0.f, rs1 = 0.f;
#pragma unroll
            for (int nt = 0; nt < 8; nt++) {
                float p0 = __expf(s[mt][nt][0] - mn0);
                float p1 = __expf(s[mt][nt][1] - mn0);
                float p2 = __expf(s[mt][nt][2] - mn1);
                float p3 = __expf(s[mt][nt][3] - mn1);
                rs0 += p0 + p1; rs1 += p2 + p3;
                s[mt][nt][0] = f2tff(p0);
                s[mt][nt][1] = f2tff(p1);
                s[mt][nt][2] = f2tff(p2);
                s[mt][nt][3] = f2tff(p3);
            }
#pragma unroll
            for (int off = 2; off >= 1; off >>= 1) {
                rs0 += __shfl_xor_sync(0xffffffffu, rs0, off);
                rs1 += __shfl_xor_sync(0xffffffffu, rs1, off);
            }
            l_[mt][0] = l_[mt][0] * al0 + rs0;
            l_[mt][1] = l_[mt][1] * al1 + rs1;
#pragma unroll
            for (int nt = 0; nt < 8; nt++) {
                o[mt][nt][0] *= al0; o[mt][nt][1] *= al0;
                o[mt][nt][2] *= al1; o[mt][nt][3] *= al1;
            }
        }

        // ---- O += P @ V : P from registers (C-frag == A-frag under perm) ----
#pragma unroll
        for (int kk = 0; kk < 8; kk++) {
#pragma unroll
            for (int nt = 0; nt < 8; nt++) {
                int addr = (kk*8 + nt)*VF_STRIDE + (vlaneoff ^ (2*((nt>>1)&1)));
                float2 b2 = *(const float2*)&Vf[addr];
#pragma unroll
                for (int mt = 0; mt < 2; mt++)
                    mma_tf32(o[mt][nt][0], o[mt][nt][1], o[mt][nt][2], o[mt][nt][3],
                             s[mt][kk][0], s[mt][kk][2], s[mt][kk][1], s[mt][kk][3],
                             b2.x, b2.y);
            }
        }
        __syncthreads();   // release buf (i&1) for prefetch of i+2
    }

    // ---- epilogue: normalize, write (B,S,H*DK) layout ----
#pragma unroll
    for (int mt = 0; mt < 2; mt++) {
        float inv0 = 1.f / l_[mt][0], inv1 = 1.f / l_[mt][1];
        int row = q0 + 32*warp + 16*mt + g;
#pragma unroll
        for (int nt = 0; nt < 8; nt++) {
            int col = nt*8 + 2*t;
            *(float2*)(Op + base + (size_t)row * D_MODEL + col) =
                make_float2(o[mt][nt][0]*inv0, o[mt][nt][1]*inv0);
            *(float2*)(Op + base + (size_t)(row + 8) * D_MODEL + col) =
                make_float2(o[mt][nt][2]*inv1, o[mt][nt][3]*inv1);
        }
    }
}

// ============================================================================
extern "C" void kernel_launch(void* const* d_in, const int* in_sizes, int n_in,
                              void* d_out, int out_size)
{
    const float* Q  = (const float*)d_in[0];
    const float* K  = (const float*)d_in[1];
    const float* V  = (const float*)d_in[2];
    const float* Wq = (const float*)d_in[3];
    const float* bq = (const float*)d_in[4];
    const float* Wk = (const float*)d_in[5];
    const float* bk = (const float*)d_in[6];
    const float* Wv = (const float*)d_in[7];
    const float* bv = (const float*)d_in[8];
    const float* Wo = (const float*)d_in[9];
    const float* bo = (const float*)d_in[10];
    float* out = (float*)d_out;

    const int M = in_sizes[0] / D_MODEL;   // B*S
    const int S = 4096;
    const int B = M / S;

    float *gq, *gk, *gv, *go;
    cudaGetSymbolAddress((void**)&gq, g_q);
    cudaGetSymbolAddress((void**)&gk, g_k);
    cudaGetSymbolAddress((void**)&gv, g_v);
    cudaGetSymbolAddress((void**)&go, g_ao);

    cudaFuncSetAttribute(flash_tc, cudaFuncAttributeMaxDynamicSharedMemorySize, SMEM_FLASH);

    dim3 tb(256);
    dim3 gg(D_MODEL / 64, M / 128);
    gemm_nt_tc<<<gg, tb>>>(Q, Wq, bq, gq, M, D_MODEL, D_MODEL, 1);
    gemm_nt_tc<<<gg, tb>>>(K, Wk, bk, gk, M, D_MODEL, D_MODEL, 2);
    gemm_nt_tc<<<gg, tb>>>(V, Wv, bv, gv, M, D_MODEL, D_MODEL, 2);

    flash_tc<<<dim3(S / 128, B * NHEAD), dim3(128), SMEM_FLASH>>>(gq, gk, gv, go, S);

    gemm_nt_tc<<<gg, tb>>>(go, Wo, bo, out, M, D_MODEL, D_MODEL, 0);
}

// round 9
// speedup vs baseline: 1.6828x; 1.3213x over previous
#include <cuda_runtime.h>
#include <cuda_fp16.h>
#include <math_constants.h>
#include <cstdint>

#define D_MODEL 768
#define NHEAD   12
#define DK      64
#define MAXM    8192   // B*S = 2*4096

// ---- scratch (no cudaMalloc allowed) ----
__device__ __half g_qh[MAXM * D_MODEL];   // q proj, fp16, *0.125*log2e, [tok][d]
__device__ __half g_kh[MAXM * D_MODEL];   // k proj, fp16, [tok][d]
__device__ __half g_vt[MAXM * D_MODEL];   // v proj, fp16, TRANSPOSED [b*768+n][s]
__device__ float  g_ao[MAXM * D_MODEL];   // attention output, fp32

#define SCALE_Q 0.1803368801111204f   // 0.125 * log2(e)

// ---- helpers ----
__device__ __forceinline__ uint32_t packh2(float lo, float hi) {
    uint32_t r; asm("cvt.rn.f16x2.f32 %0, %1, %2;" : "=r"(r) : "f"(hi), "f"(lo));
    return r;
}
__device__ __forceinline__ void mma_h(
    float& c0, float& c1, float& c2, float& c3,
    uint32_t a0, uint32_t a1, uint32_t a2, uint32_t a3,
    uint32_t b0, uint32_t b1)
{
    asm volatile(
        "mma.sync.aligned.m16n8k16.row.col.f32.f16.f16.f32 "
        "{%0,%1,%2,%3},{%4,%5,%6,%7},{%8,%9},{%0,%1,%2,%3};"
        : "+f"(c0), "+f"(c1), "+f"(c2), "+f"(c3)
        : "r"(a0), "r"(a1), "r"(a2), "r"(a3), "r"(b0), "r"(b1));
}
__device__ __forceinline__ uint32_t smem_u32(const void* p) {
    uint32_t a;
    asm("{ .reg .u64 t; cvta.to.shared.u64 t, %1; cvt.u32.u64 %0, t; }"
        : "=r"(a) : "l"(p));
    return a;
}
__device__ __forceinline__ void cpasync4(uint32_t dst, const void* src) {
    asm volatile("cp.async.ca.shared.global [%0], [%1], 4;"
                 :: "r"(dst), "l"(src) : "memory");
}
#define CP_COMMIT() asm volatile("cp.async.commit_group;" ::: "memory")
#define CP_WAIT1()  asm volatile("cp.async.wait_group 1;" ::: "memory")

// ============================================================================
// fp16 NT GEMM: C[m][n] = epilogue(bias[n] + sum_k A[m][k]*W[n][k])
// A,W fp32 in global, converted to fp16 at staging. m16n8k16 mma.
// Tile 128x64x32, 256 threads (8 warps, 4m x 2n), warp tile 32x32.
// modes: 0 = f32 out; 1 = half out *SCALE_Q; 2 = half out; 3 = half out, V^T.
// Block layouts (per mma block, 128 u4 + 4 pad):
//   A block (16r x 16k): addr = (4*(r%8) + (kp2%4))*4 + (r%16)/8 + 2*(kp2/4)
//     where kp2 = (k%16)/2  -> lane l=4g+t loads LDS.128 at l*4
//   W block (8n x 32k):  addr = (4*(n%8) + (kp2%4))*4 + ((k%16)/8) + 2*((k%32)/16)
// ============================================================================
#define BSA4 132
#define BSW4 132

__global__ __launch_bounds__(256) void gemm_h(
    const float* __restrict__ A, const float* __restrict__ W,
    const float* __restrict__ bias, void* __restrict__ Cout,
    int M, int N, int K, int mode, int S)
{
    __shared__ uint32_t Af4[16 * BSA4];
    __shared__ uint32_t Wf4[8 * BSW4];

    const int tid  = threadIdx.x;
    const int lane = tid & 31, warp = tid >> 5;
    const int g = lane >> 2, t = lane & 3;
    const int rm = warp >> 1, wn = warp & 1;
    const int bm = blockIdx.y * 128, bn = blockIdx.x * 64;

    float c[2][4][4] = {};

    for (int k0 = 0; k0 < K; k0 += 32) {
        // stage A (128x32 f32 -> f16 fragment pack)
#pragma unroll
        for (int p = 0; p < 4; p++) {
            int fl = p * 256 + tid;
            int r = fl >> 3, cc = (fl & 7) << 2;
            float4 v = *(const float4*)(A + (size_t)(bm + r) * K + k0 + cc);
            uint32_t u0 = packh2(v.x, v.y), u1 = packh2(v.z, v.w);
            int blk = (r >> 4) * 2 + (cc >> 4);
            int idx = blk * BSA4 + (4 * (r & 7) + ((cc >> 1) & 3)) * 4
                    + ((r >> 3) & 1) + 2 * ((cc >> 3) & 1);
            Af4[idx] = u0; Af4[idx + 4] = u1;
        }
        // stage W (64x32)
#pragma unroll
        for (int p = 0; p < 2; p++) {
            int fl = p * 256 + tid;
            int r = fl >> 3, cc = (fl & 7) << 2;
            float4 v = *(const float4*)(W + (size_t)(bn + r) * K + k0 + cc);
            uint32_t u0 = packh2(v.x, v.y), u1 = packh2(v.z, v.w);
            int idx = (r >> 3) * BSW4 + (4 * (r & 7) + ((cc >> 1) & 3)) * 4
                    + ((cc >> 4) & 1) * 2 + ((cc >> 3) & 1);
            Wf4[idx] = u0; Wf4[idx + 4] = u1;
        }
        __syncthreads();

        uint4 aa[2][2];
#pragma unroll
        for (int mt = 0; mt < 2; mt++)
#pragma unroll
            for (int ks = 0; ks < 2; ks++)
                aa[mt][ks] = *(const uint4*)&Af4[((rm*2 + mt)*2 + ks)*BSA4 + lane*4];
#pragma unroll
        for (int nt = 0; nt < 4; nt++) {
            uint4 b4 = *(const uint4*)&Wf4[(wn*4 + nt)*BSW4 + lane*4];
#pragma unroll
            for (int mt = 0; mt < 2; mt++) {
                mma_h(c[mt][nt][0], c[mt][nt][1], c[mt][nt][2], c[mt][nt][3],
                      aa[mt][0].x, aa[mt][0].y, aa[mt][0].z, aa[mt][0].w, b4.x, b4.y);
                mma_h(c[mt][nt][0], c[mt][nt][1], c[mt][nt][2], c[mt][nt][3],
                      aa[mt][1].x, aa[mt][1].y, aa[mt][1].z, aa[mt][1].w, b4.z, b4.w);
            }
        }
        __syncthreads();
    }

    // epilogue
#pragma unroll
    for (int mt = 0; mt < 2; mt++) {
#pragma unroll
        for (int nt = 0; nt < 4; nt++) {
            int row = bm + rm*32 + mt*16 + g;
            int col = bn + wn*32 + nt*8 + 2*t;
            float2 b2 = *(const float2*)(bias + col);
            float v0 = c[mt][nt][0] + b2.x, v1 = c[mt][nt][1] + b2.y;
            float v2 = c[mt][nt][2] + b2.x, v3 = c[mt][nt][3] + b2.y;
            if (mode == 0) {
                float* C = (float*)Cout;
                *(float2*)(C + (size_t)row * N + col) = make_float2(v0, v1);
                *(float2*)(C + (size_t)(row + 8) * N + col) = make_float2(v2, v3);
            } else if (mode == 3) {
                __half* C = (__half*)Cout;
                int b0r = row / S, s0 = row - b0r * S;
                size_t r0 = (size_t)(b0r * 768 + col) * S;
                C[r0 + s0] = __float2half(v0);
                C[r0 + S + s0] = __float2half(v1);
                C[r0 + s0 + 8] = __float2half(v2);       // row+8: same b, s+8
                C[r0 + S + s0 + 8] = __float2half(v3);
            } else {
                float sc = (mode == 1) ? SCALE_Q : 1.0f;
                __half* C = (__half*)Cout;
                *(uint32_t*)(C + (size_t)row * N + col) = packh2(v0 * sc, v1 * sc);
                *(uint32_t*)(C + (size_t)(row + 8) * N + col) = packh2(v2 * sc, v3 * sc);
            }
        }
    }
}

// ============================================================================
// fp16 flash attention. 128 threads, warp owns 32 q-rows, CTA = 128 rows.
// KV tile 64 keys, double-buffered cp.async straight into fragment layouts.
// P: QK^T C-frag packs directly into PV A-frag (no permutation, fp16).
// smem (4B units): Q 4096 | K0 2048 | K1 2048 | V0 2048 | V1 2048 = 48KB
// ============================================================================
#define FQ  0
#define FK0 4096
#define FK1 6144
#define FV0 8192
#define FV1 10240

__global__ __launch_bounds__(128) void flash_h(
    const __half* __restrict__ Qg, const __half* __restrict__ Kg,
    const __half* __restrict__ Vtg, float* __restrict__ Op, int S)
{
    __shared__ uint32_t sm4[12288];
    const uint32_t smb = smem_u32(sm4);

    const int tid  = threadIdx.x;
    const int lane = tid & 31, warp = tid >> 5;
    const int g = lane >> 2, t = lane & 3;
    const int b = blockIdx.y / NHEAD, h = blockIdx.y % NHEAD;
    const int q0 = blockIdx.x * 128;
    const __half* qbase = Qg + ((size_t)b * S) * D_MODEL + h * DK;
    const __half* kbase = Kg + ((size_t)b * S) * D_MODEL + h * DK;
    const __half* vbase = Vtg + (size_t)(b * 768 + h * 64) * S;

    // ---- stage Q via cp.async (fragment pack; 32 ops/thread) ----
#pragma unroll
    for (int j = 0; j < 32; j++) {
        int fl = j * 128 + tid;
        int r = fl >> 5, cp = fl & 31;           // c = 2*cp
        int idx = ((r >> 4) * 4 + (cp >> 3)) * 128
                + (4 * (r & 7) + (cp & 3)) * 4
                + ((r >> 3) & 1) + 2 * ((cp >> 2) & 1);
        cpasync4(smb + (FQ + idx) * 4, qbase + (size_t)(q0 + r) * D_MODEL + 2 * cp);
    }

    float o[2][8][4] = {};
    float m_[2][2], l_[2][2];
#pragma unroll
    for (int mt = 0; mt < 2; mt++) {
        m_[mt][0] = m_[mt][1] = -CUDART_INF_F;
        l_[mt][0] = l_[mt][1] = 0.f;
    }

    // prefetch tile 0
    {
#pragma unroll
        for (int j = 0; j < 16; j++) {
            int fl = j * 128 + tid;
            int r = fl >> 5, cp = fl & 31;
            int idx = ((cp >> 4) * 8 + (r >> 3)) * 128
                    + (4 * (r & 7) + (cp & 3)) * 4
                    + ((cp >> 3) & 1) * 2 + ((cp >> 2) & 1);
            cpasync4(smb + (FK0 + idx) * 4, kbase + (size_t)r * D_MODEL + 2 * cp);
        }
#pragma unroll
        for (int j = 0; j < 16; j++) {
            int fl = j * 128 + tid;
            int d = fl >> 5, kp = fl & 31;
            int idx = ((kp >> 4) * 8 + (d >> 3)) * 128
                    + (4 * (d & 7) + (kp & 3)) * 4
                    + ((kp >> 3) & 1) * 2 + ((kp >> 2) & 1);
            cpasync4(smb + (FV0 + idx) * 4, vbase + (size_t)d * S + 2 * kp);
        }
    }
    CP_COMMIT();

    const int niter = S / 64;
    for (int i = 0; i < niter; i++) {
        if (i + 1 < niter) {
            int fk = ((i + 1) & 1) ? FK1 : FK0;
            int fv = ((i + 1) & 1) ? FV1 : FV0;
            const __half* kg = kbase + (size_t)(i + 1) * 64 * D_MODEL;
            const __half* vg = vbase + (size_t)(i + 1) * 64;
#pragma unroll
            for (int j = 0; j < 16; j++) {
                int fl = j * 128 + tid;
                int r = fl >> 5, cp = fl & 31;
                int idx = ((cp >> 4) * 8 + (r >> 3)) * 128
                        + (4 * (r & 7) + (cp & 3)) * 4
                        + ((cp >> 3) & 1) * 2 + ((cp >> 2) & 1);
                cpasync4(smb + (fk + idx) * 4, kg + (size_t)r * D_MODEL + 2 * cp);
            }
#pragma unroll
            for (int j = 0; j < 16; j++) {
                int fl = j * 128 + tid;
                int d = fl >> 5, kp = fl & 31;
                int idx = ((kp >> 4) * 8 + (d >> 3)) * 128
                        + (4 * (d & 7) + (kp & 3)) * 4
                        + ((kp >> 3) & 1) * 2 + ((kp >> 2) & 1);
                cpasync4(smb + (fv + idx) * 4, vg + (size_t)d * S + 2 * kp);
            }
        }
        CP_COMMIT();
        CP_WAIT1();
        __syncthreads();

        const int fk = (i & 1) ? FK1 : FK0;
        const int fv = (i & 1) ? FV1 : FV0;

        // ---- S = Q @ K^T : 64 m16n8k16 per warp ----
        float s[2][8][4] = {};
#pragma unroll
        for (int sp = 0; sp < 2; sp++) {
            uint4 qa[2][2];
#pragma unroll
            for (int mt = 0; mt < 2; mt++) {
                qa[mt][0] = *(const uint4*)&sm4[FQ + ((warp*2 + mt)*4 + 2*sp    )*128 + lane*4];
                qa[mt][1] = *(const uint4*)&sm4[FQ + ((warp*2 + mt)*4 + 2*sp + 1)*128 + lane*4];
            }
#pragma unroll
            for (int nt = 0; nt < 8; nt++) {
                uint4 b4 = *(const uint4*)&sm4[fk + (sp*8 + nt)*128 + lane*4];
#pragma unroll
                for (int mt = 0; mt < 2; mt++) {
                    mma_h(s[mt][nt][0], s[mt][nt][1], s[mt][nt][2], s[mt][nt][3],
                          qa[mt][0].x, qa[mt][0].y, qa[mt][0].z, qa[mt][0].w, b4.x, b4.y);
                    mma_h(s[mt][nt][0], s[mt][nt][1], s[mt][nt][2], s[mt][nt][3],
                          qa[mt][1].x, qa[mt][1].y, qa[mt][1].z, qa[mt][1].w, b4.z, b4.w);
                }
            }
        }

        // ---- online softmax; pack P to fp16 pairs ----
        uint32_t pp[2][8][2];
#pragma unroll
        for (int mt = 0; mt < 2; mt++) {
            float mx0 = -CUDART_INF_F, mx1 = -CUDART_INF_F;
#pragma unroll
            for (int nt = 0; nt < 8; nt++) {
                mx0 = fmaxf(mx0, fmaxf(s[mt][nt][0], s[mt][nt][1]));
                mx1 = fmaxf(mx1, fmaxf(s[mt][nt][2], s[mt][nt][3]));
            }
#pragma unroll
            for (int off = 2; off >= 1; off >>= 1) {
                mx0 = fmaxf(mx0, __shfl_xor_sync(0xffffffffu, mx0, off));
                mx1 = fmaxf(mx1, __shfl_xor_sync(0xffffffffu, mx1, off));
            }
            float mn0 = fmaxf(m_[mt][0], mx0), mn1 = fmaxf(m_[mt][1], mx1);
            float al0 = exp2f(m_[mt][0] - mn0), al1 = exp2f(m_[mt][1] - mn1);
            m_[mt][0] = mn0; m_[mt][1] = mn1;

            float rs0 = 0.f, rs1 = 0.f;
#pragma unroll
            for (int nt = 0; nt < 8; nt++) {
                float p0 = exp2f(s[mt][nt][0] - mn0);
                float p1 = exp2f(s[mt][nt][1] - mn0);
                float p2 = exp2f(s[mt][nt][2] - mn1);
                float p3 = exp2f(s[mt][nt][3] - mn1);
                rs0 += p0 + p1; rs1 += p2 + p3;
                pp[mt][nt][0] = packh2(p0, p1);
                pp[mt][nt][1] = packh2(p2, p3);
            }
#pragma unroll
            for (int off = 2; off >= 1; off >>= 1) {
                rs0 += __shfl_xor_sync(0xffffffffu, rs0, off);
                rs1 += __shfl_xor_sync(0xffffffffu, rs1, off);
            }
            l_[mt][0] = l_[mt][0] * al0 + rs0;
            l_[mt][1] = l_[mt][1] * al1 + rs1;
#pragma unroll
            for (int nt = 0; nt < 8; nt++) {
                o[mt][nt][0] *= al0; o[mt][nt][1] *= al0;
                o[mt][nt][2] *= al1; o[mt][nt][3] *= al1;
            }
        }

        // ---- O += P @ V : 64 m16n8k16 per warp, P from registers ----
#pragma unroll
        for (int sp = 0; sp < 2; sp++) {
#pragma unroll
            for (int nt = 0; nt < 8; nt++) {
                uint4 b4 = *(const uint4*)&sm4[fv + (sp*8 + nt)*128 + lane*4];
#pragma unroll
                for (int mt = 0; mt < 2; mt++) {
                    // k16#0 of this 32-key slab: A-frag from score n-tiles (4sp, 4sp+1)
                    mma_h(o[mt][nt][0], o[mt][nt][1], o[mt][nt][2], o[mt][nt][3],
                          pp[mt][4*sp][0], pp[mt][4*sp][1],
                          pp[mt][4*sp+1][0], pp[mt][4*sp+1][1], b4.x, b4.y);
                    // k16#1: from n-tiles (4sp+2, 4sp+3)
                    mma_h(o[mt][nt][0], o[mt][nt][1], o[mt][nt][2], o[mt][nt][3],
                          pp[mt][4*sp+2][0], pp[mt][4*sp+2][1],
                          pp[mt][4*sp+3][0], pp[mt][4*sp+3][1], b4.z, b4.w);
                }
            }
        }
        __syncthreads();
    }

    // ---- epilogue: normalize, write (B,S,768) f32 ----
    float* obase = Op + ((size_t)b * S) * D_MODEL + h * DK;
#pragma unroll
    for (int mt = 0; mt < 2; mt++) {
        float inv0 = 1.f / l_[mt][0], inv1 = 1.f / l_[mt][1];
        int row = q0 + 32*warp + 16*mt + g;
#pragma unroll
        for (int nt = 0; nt < 8; nt++) {
            int col = nt*8 + 2*t;
            *(float2*)(obase + (size_t)row * D_MODEL + col) =
                make_float2(o[mt][nt][0]*inv0, o[mt][nt][1]*inv0);
            *(float2*)(obase + (size_t)(row + 8) * D_MODEL + col) =
                make_float2(o[mt][nt][2]*inv1, o[mt][nt][3]*inv1);
        }
    }
}

// ============================================================================
extern "C" void kernel_launch(void* const* d_in, const int* in_sizes, int n_in,
                              void* d_out, int out_size)
{
    const float* Q  = (const float*)d_in[0];
    const float* K  = (const float*)d_in[1];
    const float* V  = (const float*)d_in[2];
    const float* Wq = (const float*)d_in[3];
    const float* bq = (const float*)d_in[4];
    const float* Wk = (const float*)d_in[5];
    const float* bk = (const float*)d_in[6];
    const float* Wv = (const float*)d_in[7];
    const float* bv = (const float*)d_in[8];
    const float* Wo = (const float*)d_in[9];
    const float* bo = (const float*)d_in[10];
    float* out = (float*)d_out;

    const int M = in_sizes[0] / D_MODEL;   // B*S
    const int S = 4096;
    const int B = M / S;

    __half *gq, *gk, *gvt;
    float *go;
    cudaGetSymbolAddress((void**)&gq,  g_qh);
    cudaGetSymbolAddress((void**)&gk,  g_kh);
    cudaGetSymbolAddress((void**)&gvt, g_vt);
    cudaGetSymbolAddress((void**)&go,  g_ao);

    dim3 tb(256);
    dim3 gg(D_MODEL / 64, M / 128);
    gemm_h<<<gg, tb>>>(Q, Wq, bq, gq,  M, D_MODEL, D_MODEL, 1, S);
    gemm_h<<<gg, tb>>>(K, Wk, bk, gk,  M, D_MODEL, D_MODEL, 2, S);
    gemm_h<<<gg, tb>>>(V, Wv, bv, gvt, M, D_MODEL, D_MODEL, 3, S);

    flash_h<<<dim3(S / 128, B * NHEAD), dim3(128)>>>(gq, gk, gvt, go, S);

    gemm_h<<<gg, tb>>>(go, Wo, bo, out, M, D_MODEL, D_MODEL, 0, S);
}

// round 10
// speedup vs baseline: 1.9796x; 1.1763x over previous
#include <cuda_runtime.h>
#include <cuda_fp16.h>
#include <math_constants.h>
#include <cstdint>

#define D_MODEL 768
#define NHEAD   12
#define DK      64
#define MAXM    8192   // B*S = 2*4096

// ---- scratch (no cudaMalloc allowed) ----
__device__ __half g_xq[MAXM * D_MODEL];      // fp16 copy of input Q
__device__ __half g_xk[MAXM * D_MODEL];      // fp16 copy of input K
__device__ __half g_xv[MAXM * D_MODEL];      // fp16 copy of input V
__device__ __half g_wq[D_MODEL * D_MODEL];   // fp16 weights
__device__ __half g_wk[D_MODEL * D_MODEL];
__device__ __half g_wv[D_MODEL * D_MODEL];
__device__ __half g_wo[D_MODEL * D_MODEL];
__device__ __half g_qh[MAXM * D_MODEL];      // q proj, fp16, *0.125*log2e
__device__ __half g_kh[MAXM * D_MODEL];      // k proj, fp16
__device__ __half g_vt[MAXM * D_MODEL];      // v proj, fp16, transposed [b*768+n][s]
__device__ __half g_aoh[MAXM * D_MODEL];     // attention output, fp16

#define SCALE_Q 0.1803368801111204f   // 0.125 * log2(e)

// ---- helpers ----
__device__ __forceinline__ uint32_t packh2(float lo, float hi) {
    uint32_t r; asm("cvt.rn.f16x2.f32 %0, %1, %2;" : "=r"(r) : "f"(hi), "f"(lo));
    return r;
}
__device__ __forceinline__ void mma_h(
    float& c0, float& c1, float& c2, float& c3,
    uint32_t a0, uint32_t a1, uint32_t a2, uint32_t a3,
    uint32_t b0, uint32_t b1)
{
    asm volatile(
        "mma.sync.aligned.m16n8k16.row.col.f32.f16.f16.f32 "
        "{%0,%1,%2,%3},{%4,%5,%6,%7},{%8,%9},{%0,%1,%2,%3};"
        : "+f"(c0), "+f"(c1), "+f"(c2), "+f"(c3)
        : "r"(a0), "r"(a1), "r"(a2), "r"(a3), "r"(b0), "r"(b1));
}
__device__ __forceinline__ uint32_t smem_u32(const void* p) {
    uint32_t a;
    asm("{ .reg .u64 t; cvta.to.shared.u64 t, %1; cvt.u32.u64 %0, t; }"
        : "=r"(a) : "l"(p));
    return a;
}
__device__ __forceinline__ void cpasync4(uint32_t dst, const void* src) {
    asm volatile("cp.async.ca.shared.global [%0], [%1], 4;"
                 :: "r"(dst), "l"(src) : "memory");
}
#define CP_COMMIT() asm volatile("cp.async.commit_group;" ::: "memory")
#define CP_WAIT1()  asm volatile("cp.async.wait_group 1;" ::: "memory")

// ============================================================================
// fp32 -> fp16 conversion (vectorized grid-stride)
// ============================================================================
__global__ __launch_bounds__(256) void cvt_f2h(
    const float4* __restrict__ src, uint2* __restrict__ dst, int n4)
{
    int i = blockIdx.x * 256 + threadIdx.x;
    int stride = gridDim.x * 256;
    for (; i < n4; i += stride) {
        float4 v = src[i];
        dst[i] = make_uint2(packh2(v.x, v.y), packh2(v.z, v.w));
    }
}

// ============================================================================
// fp16 NT GEMM, cp.async double-buffered: C[m][n] = epi(bias[n] + A·W^T)
// A: MxK fp16, W: NxK fp16. Tile 128x64x32, 256 threads (8 warps 4m x 2n).
// modes: 0 = f32 out; 1 = half out *SCALE_Q; 2 = half out; 3 = half out V^T.
// Fragment-layout blocks (128 u4 + 4 pad); staged via 4B cp.async.
// ============================================================================
#define BSA4 132
#define BSW4 132
#define ABUF (16 * BSA4)
#define WBUF (8 * BSW4)

__global__ __launch_bounds__(256) void gemm_h(
    const __half* __restrict__ A, const __half* __restrict__ W,
    const float* __restrict__ bias, void* __restrict__ Cout,
    int M, int N, int K, int mode, int S)
{
    __shared__ uint32_t Af4[2 * ABUF];
    __shared__ uint32_t Wf4[2 * WBUF];
    const uint32_t sa = smem_u32(Af4), sw = smem_u32(Wf4);

    const int tid  = threadIdx.x;
    const int lane = tid & 31, warp = tid >> 5;
    const int g = lane >> 2, t = lane & 3;
    const int rm = warp >> 1, wn = warp & 1;
    const int bm = blockIdx.y * 128, bn = blockIdx.x * 64;

    // staging thread mapping (computed once)
    // A: 2048 u4, 8/thread ; W: 1024 u4, 4/thread
    float c[2][4][4] = {};

    const int niter = K / 32;
    // prefetch iter 0 into buf 0
    {
#pragma unroll
        for (int j = 0; j < 8; j++) {
            int fl = j * 256 + tid;
            int r = fl >> 4, cp = fl & 15;
            int idx = ((r >> 4) * 2 + (cp >> 3)) * BSA4
                    + (4 * (r & 7) + (cp & 3)) * 4
                    + ((r >> 3) & 1) + 2 * ((cp >> 2) & 1);
            cpasync4(sa + idx * 4, A + (size_t)(bm + r) * K + 2 * cp);
        }
#pragma unroll
        for (int j = 0; j < 4; j++) {
            int fl = j * 256 + tid;
            int r = fl >> 4, cp = fl & 15;
            int idx = (r >> 3) * BSW4
                    + (4 * (r & 7) + (cp & 3)) * 4
                    + ((cp >> 3) & 1) * 2 + ((cp >> 2) & 1);
            cpasync4(sw + idx * 4, W + (size_t)(bn + r) * K + 2 * cp);
        }
    }
    CP_COMMIT();

    for (int it = 0; it < niter; it++) {
        if (it + 1 < niter) {
            int k0 = (it + 1) * 32;
            uint32_t da = sa + ((it + 1) & 1) * ABUF * 4;
            uint32_t dw = sw + ((it + 1) & 1) * WBUF * 4;
#pragma unroll
            for (int j = 0; j < 8; j++) {
                int fl = j * 256 + tid;
                int r = fl >> 4, cp = fl & 15;
                int idx = ((r >> 4) * 2 + (cp >> 3)) * BSA4
                        + (4 * (r & 7) + (cp & 3)) * 4
                        + ((r >> 3) & 1) + 2 * ((cp >> 2) & 1);
                cpasync4(da + idx * 4, A + (size_t)(bm + r) * K + k0 + 2 * cp);
            }
#pragma unroll
            for (int j = 0; j < 4; j++) {
                int fl = j * 256 + tid;
                int r = fl >> 4, cp = fl & 15;
                int idx = (r >> 3) * BSW4
                        + (4 * (r & 7) + (cp & 3)) * 4
                        + ((cp >> 3) & 1) * 2 + ((cp >> 2) & 1);
                cpasync4(dw + idx * 4, W + (size_t)(bn + r) * K + k0 + 2 * cp);
            }
        }
        CP_COMMIT();
        CP_WAIT1();
        __syncthreads();

        const uint32_t* Ab = Af4 + (it & 1) * ABUF;
        const uint32_t* Wb = Wf4 + (it & 1) * WBUF;

        uint4 aa[2][2];
#pragma unroll
        for (int mt = 0; mt < 2; mt++)
#pragma unroll
            for (int ks = 0; ks < 2; ks++)
                aa[mt][ks] = *(const uint4*)&Ab[((rm*2 + mt)*2 + ks)*BSA4 + lane*4];
#pragma unroll
        for (int nt = 0; nt < 4; nt++) {
            uint4 b4 = *(const uint4*)&Wb[(wn*4 + nt)*BSW4 + lane*4];
#pragma unroll
            for (int mt = 0; mt < 2; mt++) {
                mma_h(c[mt][nt][0], c[mt][nt][1], c[mt][nt][2], c[mt][nt][3],
                      aa[mt][0].x, aa[mt][0].y, aa[mt][0].z, aa[mt][0].w, b4.x, b4.y);
                mma_h(c[mt][nt][0], c[mt][nt][1], c[mt][nt][2], c[mt][nt][3],
                      aa[mt][1].x, aa[mt][1].y, aa[mt][1].z, aa[mt][1].w, b4.z, b4.w);
            }
        }
        __syncthreads();
    }

    // epilogue
#pragma unroll
    for (int mt = 0; mt < 2; mt++) {
#pragma unroll
        for (int nt = 0; nt < 4; nt++) {
            int row = bm + rm*32 + mt*16 + g;
            int col = bn + wn*32 + nt*8 + 2*t;
            float2 b2 = *(const float2*)(bias + col);
            float v0 = c[mt][nt][0] + b2.x, v1 = c[mt][nt][1] + b2.y;
            float v2 = c[mt][nt][2] + b2.x, v3 = c[mt][nt][3] + b2.y;
            if (mode == 0) {
                float* C = (float*)Cout;
                *(float2*)(C + (size_t)row * N + col) = make_float2(v0, v1);
                *(float2*)(C + (size_t)(row + 8) * N + col) = make_float2(v2, v3);
            } else if (mode == 3) {
                __half* C = (__half*)Cout;
                int b0r = row / S, s0 = row - b0r * S;
                size_t r0 = (size_t)(b0r * 768 + col) * S;
                C[r0 + s0] = __float2half(v0);
                C[r0 + S + s0] = __float2half(v1);
                C[r0 + s0 + 8] = __float2half(v2);
                C[r0 + S + s0 + 8] = __float2half(v3);
            } else {
                float sc = (mode == 1) ? SCALE_Q : 1.0f;
                __half* C = (__half*)Cout;
                *(uint32_t*)(C + (size_t)row * N + col) = packh2(v0 * sc, v1 * sc);
                *(uint32_t*)(C + (size_t)(row + 8) * N + col) = packh2(v2 * sc, v3 * sc);
            }
        }
    }
}

// ============================================================================
// fp16 flash attention (round-9 proven). 128 threads, warp owns 32 q-rows,
// CTA = 128 rows, KV tile 64 keys, double-buffered cp.async.
// Output now fp16 [tok][768].
// ============================================================================
#define FQ  0
#define FK0 4096
#define FK1 6144
#define FV0 8192
#define FV1 10240

__global__ __launch_bounds__(128) void flash_h(
    const __half* __restrict__ Qg, const __half* __restrict__ Kg,
    const __half* __restrict__ Vtg, __half* __restrict__ Op, int S)
{
    __shared__ uint32_t sm4[12288];
    const uint32_t smb = smem_u32(sm4);

    const int tid  = threadIdx.x;
    const int lane = tid & 31, warp = tid >> 5;
    const int g = lane >> 2, t = lane & 3;
    const int b = blockIdx.y / NHEAD, h = blockIdx.y % NHEAD;
    const int q0 = blockIdx.x * 128;
    const __half* qbase = Qg + ((size_t)b * S) * D_MODEL + h * DK;
    const __half* kbase = Kg + ((size_t)b * S) * D_MODEL + h * DK;
    const __half* vbase = Vtg + (size_t)(b * 768 + h * 64) * S;

    // stage Q (fragment pack)
#pragma unroll
    for (int j = 0; j < 32; j++) {
        int fl = j * 128 + tid;
        int r = fl >> 5, cp = fl & 31;
        int idx = ((r >> 4) * 4 + (cp >> 3)) * 128
                + (4 * (r & 7) + (cp & 3)) * 4
                + ((r >> 3) & 1) + 2 * ((cp >> 2) & 1);
        cpasync4(smb + (FQ + idx) * 4, qbase + (size_t)(q0 + r) * D_MODEL + 2 * cp);
    }

    float o[2][8][4] = {};
    float m_[2][2], l_[2][2];
#pragma unroll
    for (int mt = 0; mt < 2; mt++) {
        m_[mt][0] = m_[mt][1] = -CUDART_INF_F;
        l_[mt][0] = l_[mt][1] = 0.f;
    }

    // prefetch tile 0
    {
#pragma unroll
        for (int j = 0; j < 16; j++) {
            int fl = j * 128 + tid;
            int r = fl >> 5, cp = fl & 31;
            int idx = ((cp >> 4) * 8 + (r >> 3)) * 128
                    + (4 * (r & 7) + (cp & 3)) * 4
                    + ((cp >> 3) & 1) * 2 + ((cp >> 2) & 1);
            cpasync4(smb + (FK0 + idx) * 4, kbase + (size_t)r * D_MODEL + 2 * cp);
        }
#pragma unroll
        for (int j = 0; j < 16; j++) {
            int fl = j * 128 + tid;
            int d = fl >> 5, kp = fl & 31;
            int idx = ((kp >> 4) * 8 + (d >> 3)) * 128
                    + (4 * (d & 7) + (kp & 3)) * 4
                    + ((kp >> 3) & 1) * 2 + ((kp >> 2) & 1);
            cpasync4(smb + (FV0 + idx) * 4, vbase + (size_t)d * S + 2 * kp);
        }
    }
    CP_COMMIT();

    const int niter = S / 64;
    for (int i = 0; i < niter; i++) {
        if (i + 1 < niter) {
            int fk = ((i + 1) & 1) ? FK1 : FK0;
            int fv = ((i + 1) & 1) ? FV1 : FV0;
            const __half* kg = kbase + (size_t)(i + 1) * 64 * D_MODEL;
            const __half* vg = vbase + (size_t)(i + 1) * 64;
#pragma unroll
            for (int j = 0; j < 16; j++) {
                int fl = j * 128 + tid;
                int r = fl >> 5, cp = fl & 31;
                int idx = ((cp >> 4) * 8 + (r >> 3)) * 128
                        + (4 * (r & 7) + (cp & 3)) * 4
                        + ((cp >> 3) & 1) * 2 + ((cp >> 2) & 1);
                cpasync4(smb + (fk + idx) * 4, kg + (size_t)r * D_MODEL + 2 * cp);
            }
#pragma unroll
            for (int j = 0; j < 16; j++) {
                int fl = j * 128 + tid;
                int d = fl >> 5, kp = fl & 31;
                int idx = ((kp >> 4) * 8 + (d >> 3)) * 128
                        + (4 * (d & 7) + (kp & 3)) * 4
                        + ((kp >> 3) & 1) * 2 + ((kp >> 2) & 1);
                cpasync4(smb + (fv + idx) * 4, vg + (size_t)d * S + 2 * kp);
            }
        }
        CP_COMMIT();
        CP_WAIT1();
        __syncthreads();

        const int fk = (i & 1) ? FK1 : FK0;
        const int fv = (i & 1) ? FV1 : FV0;

        // S = Q @ K^T
        float s[2][8][4] = {};
#pragma unroll
        for (int sp = 0; sp < 2; sp++) {
            uint4 qa[2][2];
#pragma unroll
            for (int mt = 0; mt < 2; mt++) {
                qa[mt][0] = *(const uint4*)&sm4[FQ + ((warp*2 + mt)*4 + 2*sp    )*128 + lane*4];
                qa[mt][1] = *(const uint4*)&sm4[FQ + ((warp*2 + mt)*4 + 2*sp + 1)*128 + lane*4];
            }
#pragma unroll
            for (int nt = 0; nt < 8; nt++) {
                uint4 b4 = *(const uint4*)&sm4[fk + (sp*8 + nt)*128 + lane*4];
#pragma unroll
                for (int mt = 0; mt < 2; mt++) {
                    mma_h(s[mt][nt][0], s[mt][nt][1], s[mt][nt][2], s[mt][nt][3],
                          qa[mt][0].x, qa[mt][0].y, qa[mt][0].z, qa[mt][0].w, b4.x, b4.y);
                    mma_h(s[mt][nt][0], s[mt][nt][1], s[mt][nt][2], s[mt][nt][3],
                          qa[mt][1].x, qa[mt][1].y, qa[mt][1].z, qa[mt][1].w, b4.z, b4.w);
                }
            }
        }

        // online softmax; pack P to fp16 pairs
        uint32_t pp[2][8][2];
#pragma unroll
        for (int mt = 0; mt < 2; mt++) {
            float mx0 = -CUDART_INF_F, mx1 = -CUDART_INF_F;
#pragma unroll
            for (int nt = 0; nt < 8; nt++) {
                mx0 = fmaxf(mx0, fmaxf(s[mt][nt][0], s[mt][nt][1]));
                mx1 = fmaxf(mx1, fmaxf(s[mt][nt][2], s[mt][nt][3]));
            }
#pragma unroll
            for (int off = 2; off >= 1; off >>= 1) {
                mx0 = fmaxf(mx0, __shfl_xor_sync(0xffffffffu, mx0, off));
                mx1 = fmaxf(mx1, __shfl_xor_sync(0xffffffffu, mx1, off));
            }
            float mn0 = fmaxf(m_[mt][0], mx0), mn1 = fmaxf(m_[mt][1], mx1);
            float al0 = exp2f(m_[mt][0] - mn0), al1 = exp2f(m_[mt][1] - mn1);
            m_[mt][0] = mn0; m_[mt][1] = mn1;

            float rs0 = 0.f, rs1 = 0.f;
#pragma unroll
            for (int nt = 0; nt < 8; nt++) {
                float p0 = exp2f(s[mt][nt][0] - mn0);
                float p1 = exp2f(s[mt][nt][1] - mn0);
                float p2 = exp2f(s[mt][nt][2] - mn1);
                float p3 = exp2f(s[mt][nt][3] - mn1);
                rs0 += p0 + p1; rs1 += p2 + p3;
                pp[mt][nt][0] = packh2(p0, p1);
                pp[mt][nt][1] = packh2(p2, p3);
            }
#pragma unroll
            for (int off = 2; off >= 1; off >>= 1) {
                rs0 += __shfl_xor_sync(0xffffffffu, rs0, off);
                rs1 += __shfl_xor_sync(0xffffffffu, rs1, off);
            }
            l_[mt][0] = l_[mt][0] * al0 + rs0;
            l_[mt][1] = l_[mt][1] * al1 + rs1;
#pragma unroll
            for (int nt = 0; nt < 8; nt++) {
                o[mt][nt][0] *= al0; o[mt][nt][1] *= al0;
                o[mt][nt][2] *= al1; o[mt][nt][3] *= al1;
            }
        }

        // O += P @ V (P from registers)
#pragma unroll
        for (int sp = 0; sp < 2; sp++) {
#pragma unroll
            for (int nt = 0; nt < 8; nt++) {
                uint4 b4 = *(const uint4*)&sm4[fv + (sp*8 + nt)*128 + lane*4];
#pragma unroll
                for (int mt = 0; mt < 2; mt++) {
                    mma_h(o[mt][nt][0], o[mt][nt][1], o[mt][nt][2], o[mt][nt][3],
                          pp[mt][4*sp][0], pp[mt][4*sp][1],
                          pp[mt][4*sp+1][0], pp[mt][4*sp+1][1], b4.x, b4.y);
                    mma_h(o[mt][nt][0], o[mt][nt][1], o[mt][nt][2], o[mt][nt][3],
                          pp[mt][4*sp+2][0], pp[mt][4*sp+2][1],
                          pp[mt][4*sp+3][0], pp[mt][4*sp+3][1], b4.z, b4.w);
                }
            }
        }
        __syncthreads();
    }

    // epilogue: normalize, write fp16 (B,S,768)
    __half* obase = Op + ((size_t)b * S) * D_MODEL + h * DK;
#pragma unroll
    for (int mt = 0; mt < 2; mt++) {
        float inv0 = 1.f / l_[mt][0], inv1 = 1.f / l_[mt][1];
        int row = q0 + 32*warp + 16*mt + g;
#pragma unroll
        for (int nt = 0; nt < 8; nt++) {
            int col = nt*8 + 2*t;
            *(uint32_t*)(obase + (size_t)row * D_MODEL + col) =
                packh2(o[mt][nt][0]*inv0, o[mt][nt][1]*inv0);
            *(uint32_t*)(obase + (size_t)(row + 8) * D_MODEL + col) =
                packh2(o[mt][nt][2]*inv1, o[mt][nt][3]*inv1);
        }
    }
}

// ============================================================================
extern "C" void kernel_launch(void* const* d_in, const int* in_sizes, int n_in,
                              void* d_out, int out_size)
{
    const float* Q  = (const float*)d_in[0];
    const float* K  = (const float*)d_in[1];
    const float* V  = (const float*)d_in[2];
    const float* Wq = (const float*)d_in[3];
    const float* bq = (const float*)d_in[4];
    const float* Wk = (const float*)d_in[5];
    const float* bk = (const float*)d_in[6];
    const float* Wv = (const float*)d_in[7];
    const float* bv = (const float*)d_in[8];
    const float* Wo = (const float*)d_in[9];
    const float* bo = (const float*)d_in[10];
    float* out = (float*)d_out;

    const int M = in_sizes[0] / D_MODEL;   // B*S
    const int S = 4096;
    const int B = M / S;

    __half *xq, *xk, *xv, *wq, *wk, *wv, *wo, *qh, *kh, *vt, *aoh;
    cudaGetSymbolAddress((void**)&xq,  g_xq);
    cudaGetSymbolAddress((void**)&xk,  g_xk);
    cudaGetSymbolAddress((void**)&xv,  g_xv);
    cudaGetSymbolAddress((void**)&wq,  g_wq);
    cudaGetSymbolAddress((void**)&wk,  g_wk);
    cudaGetSymbolAddress((void**)&wv,  g_wv);
    cudaGetSymbolAddress((void**)&wo,  g_wo);
    cudaGetSymbolAddress((void**)&qh,  g_qh);
    cudaGetSymbolAddress((void**)&kh,  g_kh);
    cudaGetSymbolAddress((void**)&vt,  g_vt);
    cudaGetSymbolAddress((void**)&aoh, g_aoh);

    const int nIn4 = (M * D_MODEL) / 4;
    const int nW4  = (D_MODEL * D_MODEL) / 4;
    cvt_f2h<<<592, 256>>>((const float4*)Q,  (uint2*)xq, nIn4);
    cvt_f2h<<<592, 256>>>((const float4*)K,  (uint2*)xk, nIn4);
    cvt_f2h<<<592, 256>>>((const float4*)V,  (uint2*)xv, nIn4);
    cvt_f2h<<<148, 256>>>((const float4*)Wq, (uint2*)wq, nW4);
    cvt_f2h<<<148, 256>>>((const float4*)Wk, (uint2*)wk, nW4);
    cvt_f2h<<<148, 256>>>((const float4*)Wv, (uint2*)wv, nW4);
    cvt_f2h<<<148, 256>>>((const float4*)Wo, (uint2*)wo, nW4);

    dim3 tb(256);
    dim3 gg(D_MODEL / 64, M / 128);
    gemm_h<<<gg, tb>>>(xq, wq, bq, qh,  M, D_MODEL, D_MODEL, 1, S);
    gemm_h<<<gg, tb>>>(xk, wk, bk, kh,  M, D_MODEL, D_MODEL, 2, S);
    gemm_h<<<gg, tb>>>(xv, wv, bv, vt,  M, D_MODEL, D_MODEL, 3, S);

    flash_h<<<dim3(S / 128, B * NHEAD), dim3(128)>>>(qh, kh, vt, aoh, S);

    gemm_h<<<gg, tb>>>(aoh, wo, bo, out, M, D_MODEL, D_MODEL, 0, S);
}

// round 11
// speedup vs baseline: 2.3806x; 1.2026x over previous
#include <cuda_runtime.h>
#include <cuda_fp16.h>
#include <math_constants.h>
#include <cstdint>

#define D_MODEL 768
#define NHEAD   12
#define DK      64
#define MAXM    8192   // B*S = 2*4096

// ---- scratch (no cudaMalloc allowed) ----
__device__ __half g_xq[MAXM * D_MODEL];      // fp16 copy of input Q
__device__ __half g_xk[MAXM * D_MODEL];      // fp16 copy of input K
__device__ __half g_xv[MAXM * D_MODEL];      // fp16 copy of input V
__device__ __half g_wq[D_MODEL * D_MODEL];   // fp16 weights
__device__ __half g_wk[D_MODEL * D_MODEL];
__device__ __half g_wv[D_MODEL * D_MODEL];
__device__ __half g_wo[D_MODEL * D_MODEL];
__device__ __half g_qh[MAXM * D_MODEL];      // q proj, fp16, *0.125*log2e
__device__ __half g_kh[MAXM * D_MODEL];      // k proj, fp16
__device__ __half g_vt[MAXM * D_MODEL];      // v proj, fp16, transposed [b*768+n][s]
__device__ __half g_aoh[MAXM * D_MODEL];     // attention output, fp16

#define SCALE_Q 0.1803368801111204f   // 0.125 * log2(e)

// ---- helpers ----
__device__ __forceinline__ uint32_t packh2(float lo, float hi) {
    uint32_t r; asm("cvt.rn.f16x2.f32 %0, %1, %2;" : "=r"(r) : "f"(hi), "f"(lo));
    return r;
}
__device__ __forceinline__ void mma_h(
    float& c0, float& c1, float& c2, float& c3,
    uint32_t a0, uint32_t a1, uint32_t a2, uint32_t a3,
    uint32_t b0, uint32_t b1)
{
    asm volatile(
        "mma.sync.aligned.m16n8k16.row.col.f32.f16.f16.f32 "
        "{%0,%1,%2,%3},{%4,%5,%6,%7},{%8,%9},{%0,%1,%2,%3};"
        : "+f"(c0), "+f"(c1), "+f"(c2), "+f"(c3)
        : "r"(a0), "r"(a1), "r"(a2), "r"(a3), "r"(b0), "r"(b1));
}
__device__ __forceinline__ uint32_t smem_u32(const void* p) {
    uint32_t a;
    asm("{ .reg .u64 t; cvta.to.shared.u64 t, %1; cvt.u32.u64 %0, t; }"
        : "=r"(a) : "l"(p));
    return a;
}
__device__ __forceinline__ void cpasync4(uint32_t dst, const void* src) {
    asm volatile("cp.async.ca.shared.global [%0], [%1], 4;"
                 :: "r"(dst), "l"(src) : "memory");
}
__device__ __forceinline__ void cpasync16(uint32_t dst, const void* src) {
    asm volatile("cp.async.cg.shared.global [%0], [%1], 16;"
                 :: "r"(dst), "l"(src) : "memory");
}
__device__ __forceinline__ void ldsm_x4(
    uint32_t& r0, uint32_t& r1, uint32_t& r2, uint32_t& r3, uint32_t addr)
{
    asm volatile("ldmatrix.sync.aligned.m8n8.x4.shared.b16 {%0,%1,%2,%3}, [%4];"
                 : "=r"(r0), "=r"(r1), "=r"(r2), "=r"(r3) : "r"(addr));
}
#define CP_COMMIT() asm volatile("cp.async.commit_group;" ::: "memory")
#define CP_WAIT1()  asm volatile("cp.async.wait_group 1;" ::: "memory")

// ============================================================================
// fp32 -> fp16 conversion (vectorized grid-stride)
// ============================================================================
__global__ __launch_bounds__(256) void cvt_f2h(
    const float4* __restrict__ src, uint2* __restrict__ dst, int n4)
{
    int i = blockIdx.x * 256 + threadIdx.x;
    int stride = gridDim.x * 256;
    for (; i < n4; i += stride) {
        float4 v = src[i];
        dst[i] = make_uint2(packh2(v.x, v.y), packh2(v.z, v.w));
    }
}

// ============================================================================
// fp16 NT GEMM, 16B cp.async + ldmatrix: C[m][n] = epi(bias[n] + A·W^T)
// A: MxK fp16, W: NxK fp16. Tile 128x128x32, 256 threads (8 warps 4m x 2n),
// warp tile 32x64. Smem: row-major 16B chunks, swizzle ch ^= (row>>1)&3.
// modes: 0 = f32 out; 1 = half out *SCALE_Q; 2 = half out; 3 = half out V^T.
// ============================================================================
__global__ __launch_bounds__(256) void gemm_h(
    const __half* __restrict__ A, const __half* __restrict__ W,
    const float* __restrict__ bias, void* __restrict__ Cout,
    int M, int N, int K, int mode, int S)
{
    __shared__ uint4 As[2][512];   // 128 rows x 4 chunks(16B) per buffer
    __shared__ uint4 Ws[2][512];
    const uint32_t sa = smem_u32(As), sw = smem_u32(Ws);

    const int tid  = threadIdx.x;
    const int lane = tid & 31, warp = tid >> 5;
    const int g = lane >> 2, t = lane & 3;
    const int rm = warp >> 1;            // m-group: rows rm*32
    const int wn = (warp & 1) * 64;      // n-base
    const int bm = blockIdx.y * 128, bn = blockIdx.x * 128;

    // ldmatrix addresses (invariant; +boff per buffer)
    uint32_t aAddr[2][2], wAddr[4][2];
#pragma unroll
    for (int mt = 0; mt < 2; mt++) {
        int ml = rm*32 + mt*16 + (lane & 15);
        int swz = (ml >> 1) & 3;
#pragma unroll
        for (int ks = 0; ks < 2; ks++) {
            int ch = ks*2 + (lane >> 4);
            aAddr[mt][ks] = sa + (uint32_t)(ml*4 + (ch ^ swz)) * 16;
        }
    }
#pragma unroll
    for (int np = 0; np < 4; np++) {
        int nl = wn + np*16 + ((lane >> 4) & 1) * 8 + (lane & 7);
        int swz = (nl >> 1) & 3;
#pragma unroll
        for (int ks = 0; ks < 2; ks++) {
            int ch = ks*2 + ((lane >> 3) & 1);
            wAddr[np][ks] = sw + (uint32_t)(nl*4 + (ch ^ swz)) * 16;
        }
    }

    float c[2][8][4] = {};

    const int niter = K / 32;
    // prefetch iter 0 into buf 0
#pragma unroll
    for (int j = 0; j < 2; j++) {
        int fl = j * 256 + tid;
        int row = fl >> 2, ch = fl & 3;
        int phys = ch ^ ((row >> 1) & 3);
        cpasync16(sa + (uint32_t)(row*4 + phys)*16, A + (size_t)(bm + row) * K + ch*8);
        cpasync16(sw + (uint32_t)(row*4 + phys)*16, W + (size_t)(bn + row) * K + ch*8);
    }
    CP_COMMIT();

    for (int it = 0; it < niter; it++) {
        if (it + 1 < niter) {
            int k0 = (it + 1) * 32;
            uint32_t bo = (uint32_t)(((it + 1) & 1) * 8192);
#pragma unroll
            for (int j = 0; j < 2; j++) {
                int fl = j * 256 + tid;
                int row = fl >> 2, ch = fl & 3;
                int phys = ch ^ ((row >> 1) & 3);
                cpasync16(sa + bo + (uint32_t)(row*4 + phys)*16,
                          A + (size_t)(bm + row) * K + k0 + ch*8);
                cpasync16(sw + bo + (uint32_t)(row*4 + phys)*16,
                          W + (size_t)(bn + row) * K + k0 + ch*8);
            }
        }
        CP_COMMIT();
        CP_WAIT1();
        __syncthreads();

        uint32_t boff = (uint32_t)((it & 1) * 8192);
#pragma unroll
        for (int ks = 0; ks < 2; ks++) {
            uint32_t a[2][4];
#pragma unroll
            for (int mt = 0; mt < 2; mt++)
                ldsm_x4(a[mt][0], a[mt][1], a[mt][2], a[mt][3], aAddr[mt][ks] + boff);
#pragma unroll
            for (int np = 0; np < 4; np++) {
                uint32_t b0, b1, b2, b3;
                ldsm_x4(b0, b1, b2, b3, wAddr[np][ks] + boff);
#pragma unroll
                for (int mt = 0; mt < 2; mt++) {
                    mma_h(c[mt][2*np][0], c[mt][2*np][1], c[mt][2*np][2], c[mt][2*np][3],
                          a[mt][0], a[mt][1], a[mt][2], a[mt][3], b0, b1);
                    mma_h(c[mt][2*np+1][0], c[mt][2*np+1][1], c[mt][2*np+1][2], c[mt][2*np+1][3],
                          a[mt][0], a[mt][1], a[mt][2], a[mt][3], b2, b3);
                }
            }
        }
        __syncthreads();
    }

    // epilogue
#pragma unroll
    for (int mt = 0; mt < 2; mt++) {
#pragma unroll
        for (int nt = 0; nt < 8; nt++) {
            int row = bm + rm*32 + mt*16 + g;
            int col = bn + wn + nt*8 + 2*t;
            float2 b2 = *(const float2*)(bias + col);
            float v0 = c[mt][nt][0] + b2.x, v1 = c[mt][nt][1] + b2.y;
            float v2 = c[mt][nt][2] + b2.x, v3 = c[mt][nt][3] + b2.y;
            if (mode == 0) {
                float* C = (float*)Cout;
                *(float2*)(C + (size_t)row * N + col) = make_float2(v0, v1);
                *(float2*)(C + (size_t)(row + 8) * N + col) = make_float2(v2, v3);
            } else if (mode == 3) {
                __half* C = (__half*)Cout;
                int b0r = row / S, s0 = row - b0r * S;
                size_t r0 = (size_t)(b0r * 768 + col) * S;
                C[r0 + s0] = __float2half(v0);
                C[r0 + S + s0] = __float2half(v1);
                C[r0 + s0 + 8] = __float2half(v2);
                C[r0 + S + s0 + 8] = __float2half(v3);
            } else {
                float sc = (mode == 1) ? SCALE_Q : 1.0f;
                __half* C = (__half*)Cout;
                *(uint32_t*)(C + (size_t)row * N + col) = packh2(v0 * sc, v1 * sc);
                *(uint32_t*)(C + (size_t)(row + 8) * N + col) = packh2(v2 * sc, v3 * sc);
            }
        }
    }
}

// ============================================================================
// fp16 flash attention (round-9/10 proven, UNCHANGED). 128 threads,
// warp owns 32 q-rows, CTA = 128 rows, KV tile 64 keys, cp.async dbuf.
// ============================================================================
#define FQ  0
#define FK0 4096
#define FK1 6144
#define FV0 8192
#define FV1 10240

__global__ __launch_bounds__(128) void flash_h(
    const __half* __restrict__ Qg, const __half* __restrict__ Kg,
    const __half* __restrict__ Vtg, __half* __restrict__ Op, int S)
{
    __shared__ uint32_t sm4[12288];
    const uint32_t smb = smem_u32(sm4);

    const int tid  = threadIdx.x;
    const int lane = tid & 31, warp = tid >> 5;
    const int g = lane >> 2, t = lane & 3;
    const int b = blockIdx.y / NHEAD, h = blockIdx.y % NHEAD;
    const int q0 = blockIdx.x * 128;
    const __half* qbase = Qg + ((size_t)b * S) * D_MODEL + h * DK;
    const __half* kbase = Kg + ((size_t)b * S) * D_MODEL + h * DK;
    const __half* vbase = Vtg + (size_t)(b * 768 + h * 64) * S;

    // stage Q (fragment pack)
#pragma unroll
    for (int j = 0; j < 32; j++) {
        int fl = j * 128 + tid;
        int r = fl >> 5, cp = fl & 31;
        int idx = ((r >> 4) * 4 + (cp >> 3)) * 128
                + (4 * (r & 7) + (cp & 3)) * 4
                + ((r >> 3) & 1) + 2 * ((cp >> 2) & 1);
        cpasync4(smb + (FQ + idx) * 4, qbase + (size_t)(q0 + r) * D_MODEL + 2 * cp);
    }

    float o[2][8][4] = {};
    float m_[2][2], l_[2][2];
#pragma unroll
    for (int mt = 0; mt < 2; mt++) {
        m_[mt][0] = m_[mt][1] = -CUDART_INF_F;
        l_[mt][0] = l_[mt][1] = 0.f;
    }

    // prefetch tile 0
    {
#pragma unroll
        for (int j = 0; j < 16; j++) {
            int fl = j * 128 + tid;
            int r = fl >> 5, cp = fl & 31;
            int idx = ((cp >> 4) * 8 + (r >> 3)) * 128
                    + (4 * (r & 7) + (cp & 3)) * 4
                    + ((cp >> 3) & 1) * 2 + ((cp >> 2) & 1);
            cpasync4(smb + (FK0 + idx) * 4, kbase + (size_t)r * D_MODEL + 2 * cp);
        }
#pragma unroll
        for (int j = 0; j < 16; j++) {
            int fl = j * 128 + tid;
            int d = fl >> 5, kp = fl & 31;
            int idx = ((kp >> 4) * 8 + (d >> 3)) * 128
                    + (4 * (d & 7) + (kp & 3)) * 4
                    + ((kp >> 3) & 1) * 2 + ((kp >> 2) & 1);
            cpasync4(smb + (FV0 + idx) * 4, vbase + (size_t)d * S + 2 * kp);
        }
    }
    CP_COMMIT();

    const int niter = S / 64;
    for (int i = 0; i < niter; i++) {
        if (i + 1 < niter) {
            int fk = ((i + 1) & 1) ? FK1 : FK0;
            int fv = ((i + 1) & 1) ? FV1 : FV0;
            const __half* kg = kbase + (size_t)(i + 1) * 64 * D_MODEL;
            const __half* vg = vbase + (size_t)(i + 1) * 64;
#pragma unroll
            for (int j = 0; j < 16; j++) {
                int fl = j * 128 + tid;
                int r = fl >> 5, cp = fl & 31;
                int idx = ((cp >> 4) * 8 + (r >> 3)) * 128
                        + (4 * (r & 7) + (cp & 3)) * 4
                        + ((cp >> 3) & 1) * 2 + ((cp >> 2) & 1);
                cpasync4(smb + (fk + idx) * 4, kg + (size_t)r * D_MODEL + 2 * cp);
            }
#pragma unroll
            for (int j = 0; j < 16; j++) {
                int fl = j * 128 + tid;
                int d = fl >> 5, kp = fl & 31;
                int idx = ((kp >> 4) * 8 + (d >> 3)) * 128
                        + (4 * (d & 7) + (kp & 3)) * 4
                        + ((kp >> 3) & 1) * 2 + ((kp >> 2) & 1);
                cpasync4(smb + (fv + idx) * 4, vg + (size_t)d * S + 2 * kp);
            }
        }
        CP_COMMIT();
        CP_WAIT1();
        __syncthreads();

        const int fk = (i & 1) ? FK1 : FK0;
        const int fv = (i & 1) ? FV1 : FV0;

        // S = Q @ K^T
        float s[2][8][4] = {};
#pragma unroll
        for (int sp = 0; sp < 2; sp++) {
            uint4 qa[2][2];
#pragma unroll
            for (int mt = 0; mt < 2; mt++) {
                qa[mt][0] = *(const uint4*)&sm4[FQ + ((warp*2 + mt)*4 + 2*sp    )*128 + lane*4];
                qa[mt][1] = *(const uint4*)&sm4[FQ + ((warp*2 + mt)*4 + 2*sp + 1)*128 + lane*4];
            }
#pragma unroll
            for (int nt = 0; nt < 8; nt++) {
                uint4 b4 = *(const uint4*)&sm4[fk + (sp*8 + nt)*128 + lane*4];
#pragma unroll
                for (int mt = 0; mt < 2; mt++) {
                    mma_h(s[mt][nt][0], s[mt][nt][1], s[mt][nt][2], s[mt][nt][3],
                          qa[mt][0].x, qa[mt][0].y, qa[mt][0].z, qa[mt][0].w, b4.x, b4.y);
                    mma_h(s[mt][nt][0], s[mt][nt][1], s[mt][nt][2], s[mt][nt][3],
                          qa[mt][1].x, qa[mt][1].y, qa[mt][1].z, qa[mt][1].w, b4.z, b4.w);
                }
            }
        }

        // online softmax; pack P to fp16 pairs
        uint32_t pp[2][8][2];
#pragma unroll
        for (int mt = 0; mt < 2; mt++) {
            float mx0 = -CUDART_INF_F, mx1 = -CUDART_INF_F;
#pragma unroll
            for (int nt = 0; nt < 8; nt++) {
                mx0 = fmaxf(mx0, fmaxf(s[mt][nt][0], s[mt][nt][1]));
                mx1 = fmaxf(mx1, fmaxf(s[mt][nt][2], s[mt][nt][3]));
            }
#pragma unroll
            for (int off = 2; off >= 1; off >>= 1) {
                mx0 = fmaxf(mx0, __shfl_xor_sync(0xffffffffu, mx0, off));
                mx1 = fmaxf(mx1, __shfl_xor_sync(0xffffffffu, mx1, off));
            }
            float mn0 = fmaxf(m_[mt][0], mx0), mn1 = fmaxf(m_[mt][1], mx1);
            float al0 = exp2f(m_[mt][0] - mn0), al1 = exp2f(m_[mt][1] - mn1);
            m_[mt][0] = mn0; m_[mt][1] = mn1;

            float rs0 = 0.f, rs1 = 0.f;
#pragma unroll
            for (int nt = 0; nt < 8; nt++) {
                float p0 = exp2f(s[mt][nt][0] - mn0);
                float p1 = exp2f(s[mt][nt][1] - mn0);
                float p2 = exp2f(s[mt][nt][2] - mn1);
                float p3 = exp2f(s[mt][nt][3] - mn1);
                rs0 += p0 + p1; rs1 += p2 + p3;
                pp[mt][nt][0] = packh2(p0, p1);
                pp[mt][nt][1] = packh2(p2, p3);
            }
#pragma unroll
            for (int off = 2; off >= 1; off >>= 1) {
                rs0 += __shfl_xor_sync(0xffffffffu, rs0, off);
                rs1 += __shfl_xor_sync(0xffffffffu, rs1, off);
            }
            l_[mt][0] = l_[mt][0] * al0 + rs0;
            l_[mt][1] = l_[mt][1] * al1 + rs1;
#pragma unroll
            for (int nt = 0; nt < 8; nt++) {
                o[mt][nt][0] *= al0; o[mt][nt][1] *= al0;
                o[mt][nt][2] *= al1; o[mt][nt][3] *= al1;
            }
        }

        // O += P @ V (P from registers)
#pragma unroll
        for (int sp = 0; sp < 2; sp++) {
#pragma unroll
            for (int nt = 0; nt < 8; nt++) {
                uint4 b4 = *(const uint4*)&sm4[fv + (sp*8 + nt)*128 + lane*4];
#pragma unroll
                for (int mt = 0; mt < 2; mt++) {
                    mma_h(o[mt][nt][0], o[mt][nt][1], o[mt][nt][2], o[mt][nt][3],
                          pp[mt][4*sp][0], pp[mt][4*sp][1],
                          pp[mt][4*sp+1][0], pp[mt][4*sp+1][1], b4.x, b4.y);
                    mma_h(o[mt][nt][0], o[mt][nt][1], o[mt][nt][2], o[mt][nt][3],
                          pp[mt][4*sp+2][0], pp[mt][4*sp+2][1],
                          pp[mt][4*sp+3][0], pp[mt][4*sp+3][1], b4.z, b4.w);
                }
            }
        }
        __syncthreads();
    }

    // epilogue: normalize, write fp16 (B,S,768)
    __half* obase = Op + ((size_t)b * S) * D_MODEL + h * DK;
#pragma unroll
    for (int mt = 0; mt < 2; mt++) {
        float inv0 = 1.f / l_[mt][0], inv1 = 1.f / l_[mt][1];
        int row = q0 + 32*warp + 16*mt + g;
#pragma unroll
        for (int nt = 0; nt < 8; nt++) {
            int col = nt*8 + 2*t;
            *(uint32_t*)(obase + (size_t)row * D_MODEL + col) =
                packh2(o[mt][nt][0]*inv0, o[mt][nt][1]*inv0);
            *(uint32_t*)(obase + (size_t)(row + 8) * D_MODEL + col) =
                packh2(o[mt][nt][2]*inv1, o[mt][nt][3]*inv1);
        }
    }
}

// ============================================================================
extern "C" void kernel_launch(void* const* d_in, const int* in_sizes, int n_in,
                              void* d_out, int out_size)
{
    const float* Q  = (const float*)d_in[0];
    const float* K  = (const float*)d_in[1];
    const float* V  = (const float*)d_in[2];
    const float* Wq = (const float*)d_in[3];
    const float* bq = (const float*)d_in[4];
    const float* Wk = (const float*)d_in[5];
    const float* bk = (const float*)d_in[6];
    const float* Wv = (const float*)d_in[7];
    const float* bv = (const float*)d_in[8];
    const float* Wo = (const float*)d_in[9];
    const float* bo = (const float*)d_in[10];
    float* out = (float*)d_out;

    const int M = in_sizes[0] / D_MODEL;   // B*S
    const int S = 4096;
    const int B = M / S;

    __half *xq, *xk, *xv, *wq, *wk, *wv, *wo, *qh, *kh, *vt, *aoh;
    cudaGetSymbolAddress((void**)&xq,  g_xq);
    cudaGetSymbolAddress((void**)&xk,  g_xk);
    cudaGetSymbolAddress((void**)&xv,  g_xv);
    cudaGetSymbolAddress((void**)&wq,  g_wq);
    cudaGetSymbolAddress((void**)&wk,  g_wk);
    cudaGetSymbolAddress((void**)&wv,  g_wv);
    cudaGetSymbolAddress((void**)&wo,  g_wo);
    cudaGetSymbolAddress((void**)&qh,  g_qh);
    cudaGetSymbolAddress((void**)&kh,  g_kh);
    cudaGetSymbolAddress((void**)&vt,  g_vt);
    cudaGetSymbolAddress((void**)&aoh, g_aoh);

    const int nIn4 = (M * D_MODEL) / 4;
    const int nW4  = (D_MODEL * D_MODEL) / 4;
    cvt_f2h<<<592, 256>>>((const float4*)Q,  (uint2*)xq, nIn4);
    cvt_f2h<<<592, 256>>>((const float4*)K,  (uint2*)xk, nIn4);
    cvt_f2h<<<592, 256>>>((const float4*)V,  (uint2*)xv, nIn4);
    cvt_f2h<<<148, 256>>>((const float4*)Wq, (uint2*)wq, nW4);
    cvt_f2h<<<148, 256>>>((const float4*)Wk, (uint2*)wk, nW4);
    cvt_f2h<<<148, 256>>>((const float4*)Wv, (uint2*)wv, nW4);
    cvt_f2h<<<148, 256>>>((const float4*)Wo, (uint2*)wo, nW4);

    dim3 tb(256);
    dim3 gg(D_MODEL / 128, M / 128);
    gemm_h<<<gg, tb>>>(xq, wq, bq, qh,  M, D_MODEL, D_MODEL, 1, S);
    gemm_h<<<gg, tb>>>(xk, wk, bk, kh,  M, D_MODEL, D_MODEL, 2, S);
    gemm_h<<<gg, tb>>>(xv, wv, bv, vt,  M, D_MODEL, D_MODEL, 3, S);

    flash_h<<<dim3(S / 128, B * NHEAD), dim3(128)>>>(qh, kh, vt, aoh, S);

    gemm_h<<<gg, tb>>>(aoh, wo, bo, out, M, D_MODEL, D_MODEL, 0, S);
}

// round 12
// speedup vs baseline: 2.7837x; 1.1693x over previous
#include <cuda_runtime.h>
#include <cuda_fp16.h>
#include <math_constants.h>
#include <cstdint>

#define D_MODEL 768
#define NHEAD   12
#define DK      64
#define MAXM    8192   // B*S = 2*4096

// ---- scratch (no cudaMalloc allowed) ----
__device__ __half g_xq[MAXM * D_MODEL];      // fp16 copy of input Q
__device__ __half g_xk[MAXM * D_MODEL];      // fp16 copy of input K
__device__ __half g_xv[MAXM * D_MODEL];      // fp16 copy of input V
__device__ __half g_wq[D_MODEL * D_MODEL];   // fp16 weights
__device__ __half g_wk[D_MODEL * D_MODEL];
__device__ __half g_wv[D_MODEL * D_MODEL];
__device__ __half g_wo[D_MODEL * D_MODEL];
__device__ __half g_qh[MAXM * D_MODEL];      // q proj, fp16, *0.125*log2e
__device__ __half g_kh[MAXM * D_MODEL];      // k proj, fp16
__device__ __half g_vt[MAXM * D_MODEL];      // v proj, fp16, transposed [b*768+n][s]
__device__ __half g_aoh[MAXM * D_MODEL];     // attention output, fp16

#define SCALE_Q 0.1803368801111204f   // 0.125 * log2(e)

// ---- helpers ----
__device__ __forceinline__ uint32_t packh2(float lo, float hi) {
    uint32_t r; asm("cvt.rn.f16x2.f32 %0, %1, %2;" : "=r"(r) : "f"(hi), "f"(lo));
    return r;
}
__device__ __forceinline__ void mma_h(
    float& c0, float& c1, float& c2, float& c3,
    uint32_t a0, uint32_t a1, uint32_t a2, uint32_t a3,
    uint32_t b0, uint32_t b1)
{
    asm volatile(
        "mma.sync.aligned.m16n8k16.row.col.f32.f16.f16.f32 "
        "{%0,%1,%2,%3},{%4,%5,%6,%7},{%8,%9},{%0,%1,%2,%3};"
        : "+f"(c0), "+f"(c1), "+f"(c2), "+f"(c3)
        : "r"(a0), "r"(a1), "r"(a2), "r"(a3), "r"(b0), "r"(b1));
}
__device__ __forceinline__ uint32_t smem_u32(const void* p) {
    uint32_t a;
    asm("{ .reg .u64 t; cvta.to.shared.u64 t, %1; cvt.u32.u64 %0, t; }"
        : "=r"(a) : "l"(p));
    return a;
}
__device__ __forceinline__ void cpasync16(uint32_t dst, const void* src) {
    asm volatile("cp.async.cg.shared.global [%0], [%1], 16;"
                 :: "r"(dst), "l"(src) : "memory");
}
__device__ __forceinline__ void ldsm_x4(
    uint32_t& r0, uint32_t& r1, uint32_t& r2, uint32_t& r3, uint32_t addr)
{
    asm volatile("ldmatrix.sync.aligned.m8n8.x4.shared.b16 {%0,%1,%2,%3}, [%4];"
                 : "=r"(r0), "=r"(r1), "=r"(r2), "=r"(r3) : "r"(addr));
}
#define CP_COMMIT() asm volatile("cp.async.commit_group;" ::: "memory")
#define CP_WAIT1()  asm volatile("cp.async.wait_group 1;" ::: "memory")

// ============================================================================
// fp32 -> fp16 conversion (vectorized grid-stride)
// ============================================================================
__global__ __launch_bounds__(256) void cvt_f2h(
    const float4* __restrict__ src, uint2* __restrict__ dst, int n4)
{
    int i = blockIdx.x * 256 + threadIdx.x;
    int stride = gridDim.x * 256;
    for (; i < n4; i += stride) {
        float4 v = src[i];
        dst[i] = make_uint2(packh2(v.x, v.y), packh2(v.z, v.w));
    }
}

// ============================================================================
// fp16 NT GEMM (round-11 proven): 16B cp.async + ldmatrix.
// Tile 128x128x32, 256 threads (8 warps 4m x 2n), warp tile 32x64.
// Smem: row-major 16B chunks, swizzle ch ^= (row>>1)&3.
// modes: 0 = f32 out; 1 = half out *SCALE_Q; 2 = half out; 3 = half out V^T.
// ============================================================================
__global__ __launch_bounds__(256) void gemm_h(
    const __half* __restrict__ A, const __half* __restrict__ W,
    const float* __restrict__ bias, void* __restrict__ Cout,
    int M, int N, int K, int mode, int S)
{
    __shared__ uint4 As[2][512];   // 128 rows x 4 chunks(16B) per buffer
    __shared__ uint4 Ws[2][512];
    const uint32_t sa = smem_u32(As), sw = smem_u32(Ws);

    const int tid  = threadIdx.x;
    const int lane = tid & 31, warp = tid >> 5;
    const int g = lane >> 2, t = lane & 3;
    const int rm = warp >> 1;
    const int wn = (warp & 1) * 64;
    const int bm = blockIdx.y * 128, bn = blockIdx.x * 128;

    uint32_t aAddr[2][2], wAddr[4][2];
#pragma unroll
    for (int mt = 0; mt < 2; mt++) {
        int ml = rm*32 + mt*16 + (lane & 15);
        int swz = (ml >> 1) & 3;
#pragma unroll
        for (int ks = 0; ks < 2; ks++) {
            int ch = ks*2 + (lane >> 4);
            aAddr[mt][ks] = sa + (uint32_t)(ml*4 + (ch ^ swz)) * 16;
        }
    }
#pragma unroll
    for (int np = 0; np < 4; np++) {
        int nl = wn + np*16 + ((lane >> 4) & 1) * 8 + (lane & 7);
        int swz = (nl >> 1) & 3;
#pragma unroll
        for (int ks = 0; ks < 2; ks++) {
            int ch = ks*2 + ((lane >> 3) & 1);
            wAddr[np][ks] = sw + (uint32_t)(nl*4 + (ch ^ swz)) * 16;
        }
    }

    float c[2][8][4] = {};

    const int niter = K / 32;
#pragma unroll
    for (int j = 0; j < 2; j++) {
        int fl = j * 256 + tid;
        int row = fl >> 2, ch = fl & 3;
        int phys = ch ^ ((row >> 1) & 3);
        cpasync16(sa + (uint32_t)(row*4 + phys)*16, A + (size_t)(bm + row) * K + ch*8);
        cpasync16(sw + (uint32_t)(row*4 + phys)*16, W + (size_t)(bn + row) * K + ch*8);
    }
    CP_COMMIT();

    for (int it = 0; it < niter; it++) {
        if (it + 1 < niter) {
            int k0 = (it + 1) * 32;
            uint32_t bo = (uint32_t)(((it + 1) & 1) * 8192);
#pragma unroll
            for (int j = 0; j < 2; j++) {
                int fl = j * 256 + tid;
                int row = fl >> 2, ch = fl & 3;
                int phys = ch ^ ((row >> 1) & 3);
                cpasync16(sa + bo + (uint32_t)(row*4 + phys)*16,
                          A + (size_t)(bm + row) * K + k0 + ch*8);
                cpasync16(sw + bo + (uint32_t)(row*4 + phys)*16,
                          W + (size_t)(bn + row) * K + k0 + ch*8);
            }
        }
        CP_COMMIT();
        CP_WAIT1();
        __syncthreads();

        uint32_t boff = (uint32_t)((it & 1) * 8192);
#pragma unroll
        for (int ks = 0; ks < 2; ks++) {
            uint32_t a[2][4];
#pragma unroll
            for (int mt = 0; mt < 2; mt++)
                ldsm_x4(a[mt][0], a[mt][1], a[mt][2], a[mt][3], aAddr[mt][ks] + boff);
#pragma unroll
            for (int np = 0; np < 4; np++) {
                uint32_t b0, b1, b2, b3;
                ldsm_x4(b0, b1, b2, b3, wAddr[np][ks] + boff);
#pragma unroll
                for (int mt = 0; mt < 2; mt++) {
                    mma_h(c[mt][2*np][0], c[mt][2*np][1], c[mt][2*np][2], c[mt][2*np][3],
                          a[mt][0], a[mt][1], a[mt][2], a[mt][3], b0, b1);
                    mma_h(c[mt][2*np+1][0], c[mt][2*np+1][1], c[mt][2*np+1][2], c[mt][2*np+1][3],
                          a[mt][0], a[mt][1], a[mt][2], a[mt][3], b2, b3);
                }
            }
        }
        __syncthreads();
    }

    // epilogue
#pragma unroll
    for (int mt = 0; mt < 2; mt++) {
#pragma unroll
        for (int nt = 0; nt < 8; nt++) {
            int row = bm + rm*32 + mt*16 + g;
            int col = bn + wn + nt*8 + 2*t;
            float2 b2 = *(const float2*)(bias + col);
            float v0 = c[mt][nt][0] + b2.x, v1 = c[mt][nt][1] + b2.y;
            float v2 = c[mt][nt][2] + b2.x, v3 = c[mt][nt][3] + b2.y;
            if (mode == 0) {
                float* C = (float*)Cout;
                *(float2*)(C + (size_t)row * N + col) = make_float2(v0, v1);
                *(float2*)(C + (size_t)(row + 8) * N + col) = make_float2(v2, v3);
            } else if (mode == 3) {
                __half* C = (__half*)Cout;
                int b0r = row / S, s0 = row - b0r * S;
                size_t r0 = (size_t)(b0r * 768 + col) * S;
                C[r0 + s0] = __float2half(v0);
                C[r0 + S + s0] = __float2half(v1);
                C[r0 + s0 + 8] = __float2half(v2);
                C[r0 + S + s0 + 8] = __float2half(v3);
            } else {
                float sc = (mode == 1) ? SCALE_Q : 1.0f;
                __half* C = (__half*)Cout;
                *(uint32_t*)(C + (size_t)row * N + col) = packh2(v0 * sc, v1 * sc);
                *(uint32_t*)(C + (size_t)(row + 8) * N + col) = packh2(v2 * sc, v3 * sc);
            }
        }
    }
}

// ============================================================================
// fp16 flash attention, 16B cp.async + ldmatrix staging.
// 128 threads, warp owns 32 q-rows, CTA = 128 rows, KV tile 64 keys.
// Smem rows = 128B (8 chunks of 16B), swizzle phys = ch ^ (row & 7).
// Q fragments hoisted to registers; P stays in registers (C-frag == A-frag).
// smem bytes: Q 16384 | K0 8192 | K1 8192 | V0 8192 | V1 8192 = 48KB
// ============================================================================
#define FQ_B  0
#define FK0_B 16384
#define FK1_B 24576
#define FV0_B 32768
#define FV1_B 40960

__global__ __launch_bounds__(128) void flash_h(
    const __half* __restrict__ Qg, const __half* __restrict__ Kg,
    const __half* __restrict__ Vtg, __half* __restrict__ Op, int S)
{
    __shared__ char smc[49152];
    const uint32_t smb = smem_u32(smc);

    const int tid  = threadIdx.x;
    const int lane = tid & 31, warp = tid >> 5;
    const int g = lane >> 2, t = lane & 3;
    const int b = blockIdx.y / NHEAD, h = blockIdx.y % NHEAD;
    const int q0 = blockIdx.x * 128;
    const __half* qbase = Qg + ((size_t)b * S) * D_MODEL + h * DK;
    const __half* kbase = Kg + ((size_t)b * S) * D_MODEL + h * DK;
    const __half* vbase = Vtg + (size_t)(b * 768 + h * 64) * S;

    // B-operand ldmatrix relative addresses (same formula for K and V tiles)
    uint32_t bAddr[4][4];
#pragma unroll
    for (int np = 0; np < 4; np++) {
        int row = np*16 + ((lane >> 4) & 1) * 8 + (lane & 7);
#pragma unroll
        for (int ks = 0; ks < 4; ks++) {
            int ch = ks*2 + ((lane >> 3) & 1);
            bAddr[np][ks] = (uint32_t)((row*8 + (ch ^ (row & 7))) * 16);
        }
    }

    // ---- stage Q (16KB) + prefetch tile 0, one group ----
#pragma unroll
    for (int j = 0; j < 8; j++) {
        int fl = j * 128 + tid;
        int row = fl >> 3, ch = fl & 7;
        int phys = ch ^ (row & 7);
        cpasync16(smb + FQ_B + (uint32_t)(row*8 + phys)*16,
                  qbase + (size_t)(q0 + row) * D_MODEL + ch*8);
    }
#pragma unroll
    for (int j = 0; j < 4; j++) {
        int fl = j * 128 + tid;
        int row = fl >> 3, ch = fl & 7;
        int phys = ch ^ (row & 7);
        cpasync16(smb + FK0_B + (uint32_t)(row*8 + phys)*16,
                  kbase + (size_t)row * D_MODEL + ch*8);
        cpasync16(smb + FV0_B + (uint32_t)(row*8 + phys)*16,
                  vbase + (size_t)row * S + ch*8);
    }
    CP_COMMIT();

    float o[2][8][4] = {};
    float m_[2][2], l_[2][2];
#pragma unroll
    for (int mt = 0; mt < 2; mt++) {
        m_[mt][0] = m_[mt][1] = -CUDART_INF_F;
        l_[mt][0] = l_[mt][1] = 0.f;
    }
    uint32_t qa[2][4][4];   // hoisted Q fragments

    const int niter = S / 64;
    for (int i = 0; i < niter; i++) {
        if (i + 1 < niter) {
            uint32_t fk = ((i + 1) & 1) ? FK1_B : FK0_B;
            uint32_t fv = ((i + 1) & 1) ? FV1_B : FV0_B;
            const __half* kg = kbase + (size_t)(i + 1) * 64 * D_MODEL;
            const __half* vg = vbase + (size_t)(i + 1) * 64;
#pragma unroll
            for (int j = 0; j < 4; j++) {
                int fl = j * 128 + tid;
                int row = fl >> 3, ch = fl & 7;
                int phys = ch ^ (row & 7);
                cpasync16(smb + fk + (uint32_t)(row*8 + phys)*16,
                          kg + (size_t)row * D_MODEL + ch*8);
                cpasync16(smb + fv + (uint32_t)(row*8 + phys)*16,
                          vg + (size_t)row * S + ch*8);
            }
        }
        CP_COMMIT();
        CP_WAIT1();
        __syncthreads();

        if (i == 0) {
            // load Q fragments once (now resident)
#pragma unroll
            for (int mt = 0; mt < 2; mt++) {
                int row = warp*32 + mt*16 + (lane & 15);
#pragma unroll
                for (int ks = 0; ks < 4; ks++) {
                    int ch = ks*2 + (lane >> 4);
                    uint32_t addr = smb + FQ_B + (uint32_t)((row*8 + (ch ^ (row & 7)))*16);
                    ldsm_x4(qa[mt][ks][0], qa[mt][ks][1], qa[mt][ks][2], qa[mt][ks][3], addr);
                }
            }
        }

        const uint32_t fk = smb + ((i & 1) ? FK1_B : FK0_B);
        const uint32_t fv = smb + ((i & 1) ? FV1_B : FV0_B);

        // ---- S = Q @ K^T ----
        float s[2][8][4] = {};
#pragma unroll
        for (int ks = 0; ks < 4; ks++) {
#pragma unroll
            for (int np = 0; np < 4; np++) {
                uint32_t b0, b1, b2, b3;
                ldsm_x4(b0, b1, b2, b3, fk + bAddr[np][ks]);
#pragma unroll
                for (int mt = 0; mt < 2; mt++) {
                    mma_h(s[mt][2*np][0], s[mt][2*np][1], s[mt][2*np][2], s[mt][2*np][3],
                          qa[mt][ks][0], qa[mt][ks][1], qa[mt][ks][2], qa[mt][ks][3], b0, b1);
                    mma_h(s[mt][2*np+1][0], s[mt][2*np+1][1], s[mt][2*np+1][2], s[mt][2*np+1][3],
                          qa[mt][ks][0], qa[mt][ks][1], qa[mt][ks][2], qa[mt][ks][3], b2, b3);
                }
            }
        }

        // ---- online softmax; pack P to fp16 pairs ----
        uint32_t pp[2][8][2];
#pragma unroll
        for (int mt = 0; mt < 2; mt++) {
            float mx0 = -CUDART_INF_F, mx1 = -CUDART_INF_F;
#pragma unroll
            for (int nt = 0; nt < 8; nt++) {
                mx0 = fmaxf(mx0, fmaxf(s[mt][nt][0], s[mt][nt][1]));
                mx1 = fmaxf(mx1, fmaxf(s[mt][nt][2], s[mt][nt][3]));
            }
#pragma unroll
            for (int off = 2; off >= 1; off >>= 1) {
                mx0 = fmaxf(mx0, __shfl_xor_sync(0xffffffffu, mx0, off));
                mx1 = fmaxf(mx1, __shfl_xor_sync(0xffffffffu, mx1, off));
            }
            float mn0 = fmaxf(m_[mt][0], mx0), mn1 = fmaxf(m_[mt][1], mx1);
            float al0 = exp2f(m_[mt][0] - mn0), al1 = exp2f(m_[mt][1] - mn1);
            m_[mt][0] = mn0; m_[mt][1] = mn1;

            float rs0 = 0.f, rs1 = 0.f;
#pragma unroll
            for (int nt = 0; nt < 8; nt++) {
                float p0 = exp2f(s[mt][nt][0] - mn0);
                float p1 = exp2f(s[mt][nt][1] - mn0);
                float p2 = exp2f(s[mt][nt][2] - mn1);
                float p3 = exp2f(s[mt][nt][3] - mn1);
                rs0 += p0 + p1; rs1 += p2 + p3;
                pp[mt][nt][0] = packh2(p0, p1);
                pp[mt][nt][1] = packh2(p2, p3);
            }
#pragma unroll
            for (int off = 2; off >= 1; off >>= 1) {
                rs0 += __shfl_xor_sync(0xffffffffu, rs0, off);
                rs1 += __shfl_xor_sync(0xffffffffu, rs1, off);
            }
            l_[mt][0] = l_[mt][0] * al0 + rs0;
            l_[mt][1] = l_[mt][1] * al1 + rs1;
#pragma unroll
            for (int nt = 0; nt < 8; nt++) {
                o[mt][nt][0] *= al0; o[mt][nt][1] *= al0;
                o[mt][nt][2] *= al1; o[mt][nt][3] *= al1;
            }
        }

        // ---- O += P @ V : P from registers; k-slab ks = keys 16ks..16ks+15 ----
#pragma unroll
        for (int ks = 0; ks < 4; ks++) {
#pragma unroll
            for (int np = 0; np < 4; np++) {
                uint32_t b0, b1, b2, b3;
                ldsm_x4(b0, b1, b2, b3, fv + bAddr[np][ks]);
#pragma unroll
                for (int mt = 0; mt < 2; mt++) {
                    mma_h(o[mt][2*np][0], o[mt][2*np][1], o[mt][2*np][2], o[mt][2*np][3],
                          pp[mt][2*ks][0], pp[mt][2*ks][1],
                          pp[mt][2*ks+1][0], pp[mt][2*ks+1][1], b0, b1);
                    mma_h(o[mt][2*np+1][0], o[mt][2*np+1][1], o[mt][2*np+1][2], o[mt][2*np+1][3],
                          pp[mt][2*ks][0], pp[mt][2*ks][1],
                          pp[mt][2*ks+1][0], pp[mt][2*ks+1][1], b2, b3);
                }
            }
        }
        __syncthreads();
    }

    // ---- epilogue: normalize, write fp16 (B,S,768) ----
    __half* obase = Op + ((size_t)b * S) * D_MODEL + h * DK;
#pragma unroll
    for (int mt = 0; mt < 2; mt++) {
        float inv0 = 1.f / l_[mt][0], inv1 = 1.f / l_[mt][1];
        int row = q0 + 32*warp + 16*mt + g;
#pragma unroll
        for (int nt = 0; nt < 8; nt++) {
            int col = nt*8 + 2*t;
            *(uint32_t*)(obase + (size_t)row * D_MODEL + col) =
                packh2(o[mt][nt][0]*inv0, o[mt][nt][1]*inv0);
            *(uint32_t*)(obase + (size_t)(row + 8) * D_MODEL + col) =
                packh2(o[mt][nt][2]*inv1, o[mt][nt][3]*inv1);
        }
    }
}

// ============================================================================
extern "C" void kernel_launch(void* const* d_in, const int* in_sizes, int n_in,
                              void* d_out, int out_size)
{
    const float* Q  = (const float*)d_in[0];
    const float* K  = (const float*)d_in[1];
    const float* V  = (const float*)d_in[2];
    const float* Wq = (const float*)d_in[3];
    const float* bq = (const float*)d_in[4];
    const float* Wk = (const float*)d_in[5];
    const float* bk = (const float*)d_in[6];
    const float* Wv = (const float*)d_in[7];
    const float* bv = (const float*)d_in[8];
    const float* Wo = (const float*)d_in[9];
    const float* bo = (const float*)d_in[10];
    float* out = (float*)d_out;

    const int M = in_sizes[0] / D_MODEL;   // B*S
    const int S = 4096;
    const int B = M / S;

    __half *xq, *xk, *xv, *wq, *wk, *wv, *wo, *qh, *kh, *vt, *aoh;
    cudaGetSymbolAddress((void**)&xq,  g_xq);
    cudaGetSymbolAddress((void**)&xk,  g_xk);
    cudaGetSymbolAddress((void**)&xv,  g_xv);
    cudaGetSymbolAddress((void**)&wq,  g_wq);
    cudaGetSymbolAddress((void**)&wk,  g_wk);
    cudaGetSymbolAddress((void**)&wv,  g_wv);
    cudaGetSymbolAddress((void**)&wo,  g_wo);
    cudaGetSymbolAddress((void**)&qh,  g_qh);
    cudaGetSymbolAddress((void**)&kh,  g_kh);
    cudaGetSymbolAddress((void**)&vt,  g_vt);
    cudaGetSymbolAddress((void**)&aoh, g_aoh);

    const int nIn4 = (M * D_MODEL) / 4;
    const int nW4  = (D_MODEL * D_MODEL) / 4;
    cvt_f2h<<<592, 256>>>((const float4*)Q,  (uint2*)xq, nIn4);
    cvt_f2h<<<592, 256>>>((const float4*)K,  (uint2*)xk, nIn4);
    cvt_f2h<<<592, 256>>>((const float4*)V,  (uint2*)xv, nIn4);
    cvt_f2h<<<148, 256>>>((const float4*)Wq, (uint2*)wq, nW4);
    cvt_f2h<<<148, 256>>>((const float4*)Wk, (uint2*)wk, nW4);
    cvt_f2h<<<148, 256>>>((const float4*)Wv, (uint2*)wv, nW4);
    cvt_f2h<<<148, 256>>>((const float4*)Wo, (uint2*)wo, nW4);

    dim3 tb(256);
    dim3 gg(D_MODEL / 128, M / 128);
    gemm_h<<<gg, tb>>>(xq, wq, bq, qh,  M, D_MODEL, D_MODEL, 1, S);
    gemm_h<<<gg, tb>>>(xk, wk, bk, kh,  M, D_MODEL, D_MODEL, 2, S);
    gemm_h<<<gg, tb>>>(xv, wv, bv, vt,  M, D_MODEL, D_MODEL, 3, S);

    flash_h<<<dim3(S / 128, B * NHEAD), dim3(128)>>>(qh, kh, vt, aoh, S);

    gemm_h<<<gg, tb>>>(aoh, wo, bo, out, M, D_MODEL, D_MODEL, 0, S);
}

// round 13
// speedup vs baseline: 2.9530x; 1.0608x over previous
#include <cuda_runtime.h>
#include <cuda_fp16.h>
#include <math_constants.h>
#include <cstdint>

#define D_MODEL 768
#define NHEAD   12
#define DK      64
#define MAXM    8192   // B*S = 2*4096

// ---- scratch (no cudaMalloc allowed) ----
__device__ __half g_xq[MAXM * D_MODEL];
__device__ __half g_xk[MAXM * D_MODEL];
__device__ __half g_xv[MAXM * D_MODEL];
__device__ __half g_wq[D_MODEL * D_MODEL];
__device__ __half g_wk[D_MODEL * D_MODEL];
__device__ __half g_wv[D_MODEL * D_MODEL];
__device__ __half g_wo[D_MODEL * D_MODEL];
__device__ __half g_qh[MAXM * D_MODEL];      // q proj, fp16, *0.125*log2e
__device__ __half g_kh[MAXM * D_MODEL];      // k proj, fp16
__device__ __half g_vt[MAXM * D_MODEL];      // v proj, fp16, transposed [b*768+n][s]
__device__ __half g_aoh[MAXM * D_MODEL];     // attention output, fp16

#define SCALE_Q 0.1803368801111204f   // 0.125 * log2(e)

// ---- helpers ----
__device__ __forceinline__ uint32_t packh2(float lo, float hi) {
    uint32_t r; asm("cvt.rn.f16x2.f32 %0, %1, %2;" : "=r"(r) : "f"(hi), "f"(lo));
    return r;
}
__device__ __forceinline__ void mma_h(
    float& c0, float& c1, float& c2, float& c3,
    uint32_t a0, uint32_t a1, uint32_t a2, uint32_t a3,
    uint32_t b0, uint32_t b1)
{
    asm volatile(
        "mma.sync.aligned.m16n8k16.row.col.f32.f16.f16.f32 "
        "{%0,%1,%2,%3},{%4,%5,%6,%7},{%8,%9},{%0,%1,%2,%3};"
        : "+f"(c0), "+f"(c1), "+f"(c2), "+f"(c3)
        : "r"(a0), "r"(a1), "r"(a2), "r"(a3), "r"(b0), "r"(b1));
}
__device__ __forceinline__ uint32_t smem_u32(const void* p) {
    uint32_t a;
    asm("{ .reg .u64 t; cvta.to.shared.u64 t, %1; cvt.u32.u64 %0, t; }"
        : "=r"(a) : "l"(p));
    return a;
}
__device__ __forceinline__ void cpasync16(uint32_t dst, const void* src) {
    asm volatile("cp.async.cg.shared.global [%0], [%1], 16;"
                 :: "r"(dst), "l"(src) : "memory");
}
__device__ __forceinline__ void ldsm_x4(
    uint32_t& r0, uint32_t& r1, uint32_t& r2, uint32_t& r3, uint32_t addr)
{
    asm volatile("ldmatrix.sync.aligned.m8n8.x4.shared.b16 {%0,%1,%2,%3}, [%4];"
                 : "=r"(r0), "=r"(r1), "=r"(r2), "=r"(r3) : "r"(addr));
}
#define CP_COMMIT() asm volatile("cp.async.commit_group;" ::: "memory")
#define CP_WAIT1()  asm volatile("cp.async.wait_group 1;" ::: "memory")

// ============================================================================
// batched fp32 -> fp16 conversion: blockIdx.y selects tensor (up to 4)
// ============================================================================
__global__ __launch_bounds__(256) void cvt_multi(
    const float4* __restrict__ s0, const float4* __restrict__ s1,
    const float4* __restrict__ s2, const float4* __restrict__ s3,
    uint2* __restrict__ d0, uint2* __restrict__ d1,
    uint2* __restrict__ d2, uint2* __restrict__ d3, int n4)
{
    const float4* s; uint2* d;
    switch (blockIdx.y) {
        case 0:  s = s0; d = d0; break;
        case 1:  s = s1; d = d1; break;
        case 2:  s = s2; d = d2; break;
        default: s = s3; d = d3; break;
    }
    int i = blockIdx.x * 256 + threadIdx.x;
    int stride = gridDim.x * 256;
    for (; i < n4; i += stride) {
        float4 v = s[i];
        d[i] = make_uint2(packh2(v.x, v.y), packh2(v.z, v.w));
    }
}

// ============================================================================
// fp16 NT GEMM, BK=64, 16B cp.async + ldmatrix, 64KB dynamic smem.
// Tile 128x128x64, 256 threads (8 warps 4m x 2n), warp tile 32x64.
// Smem rows = 128B (8 chunks), swizzle phys = ch ^ (row & 7).
// modes: 0 = f32 out; 1 = half out *SCALE_Q; 2 = half out; 3 = half out V^T.
// ============================================================================
#define GA0 0
#define GA1 16384
#define GW0 32768
#define GW1 49152
#define GEMM_SMEM 65536

__global__ __launch_bounds__(256) void gemm_h(
    const __half* __restrict__ A, const __half* __restrict__ W,
    const float* __restrict__ bias, void* __restrict__ Cout,
    int M, int N, int K, int mode, int S)
{
    extern __shared__ char gsm[];
    const uint32_t sb = smem_u32(gsm);

    const int tid  = threadIdx.x;
    const int lane = tid & 31, warp = tid >> 5;
    const int g = lane >> 2, t = lane & 3;
    const int rm = warp >> 1;
    const int wn = (warp & 1) * 64;
    const int bm = blockIdx.y * 128, bn = blockIdx.x * 128;

    // relative ldsm addresses (row*8 + (ch ^ (row&7))) * 16
    uint32_t aAddr[2][4], wAddr[4][4];
#pragma unroll
    for (int mt = 0; mt < 2; mt++) {
        int row = rm*32 + mt*16 + (lane & 15);
#pragma unroll
        for (int ks = 0; ks < 4; ks++) {
            int ch = ks*2 + (lane >> 4);
            aAddr[mt][ks] = (uint32_t)((row*8 + (ch ^ (row & 7))) * 16);
        }
    }
#pragma unroll
    for (int np = 0; np < 4; np++) {
        int row = wn + np*16 + ((lane >> 4) & 1) * 8 + (lane & 7);
#pragma unroll
        for (int ks = 0; ks < 4; ks++) {
            int ch = ks*2 + ((lane >> 3) & 1);
            wAddr[np][ks] = (uint32_t)((row*8 + (ch ^ (row & 7))) * 16);
        }
    }

    float c[2][8][4] = {};

    const int niter = K / 64;
    // prefetch iter 0 into buf 0
#pragma unroll
    for (int j = 0; j < 4; j++) {
        int fl = j * 256 + tid;
        int row = fl >> 3, ch = fl & 7;
        int phys = ch ^ (row & 7);
        cpasync16(sb + GA0 + (uint32_t)(row*8 + phys)*16, A + (size_t)(bm + row) * K + ch*8);
        cpasync16(sb + GW0 + (uint32_t)(row*8 + phys)*16, W + (size_t)(bn + row) * K + ch*8);
    }
    CP_COMMIT();

    for (int it = 0; it < niter; it++) {
        if (it + 1 < niter) {
            int k0 = (it + 1) * 64;
            uint32_t da = sb + (((it + 1) & 1) ? GA1 : GA0);
            uint32_t dw = sb + (((it + 1) & 1) ? GW1 : GW0);
#pragma unroll
            for (int j = 0; j < 4; j++) {
                int fl = j * 256 + tid;
                int row = fl >> 3, ch = fl & 7;
                int phys = ch ^ (row & 7);
                cpasync16(da + (uint32_t)(row*8 + phys)*16,
                          A + (size_t)(bm + row) * K + k0 + ch*8);
                cpasync16(dw + (uint32_t)(row*8 + phys)*16,
                          W + (size_t)(bn + row) * K + k0 + ch*8);
            }
        }
        CP_COMMIT();
        CP_WAIT1();
        __syncthreads();

        uint32_t ba = sb + ((it & 1) ? GA1 : GA0);
        uint32_t bw = sb + ((it & 1) ? GW1 : GW0);
#pragma unroll
        for (int ks = 0; ks < 4; ks++) {
            uint32_t a[2][4];
#pragma unroll
            for (int mt = 0; mt < 2; mt++)
                ldsm_x4(a[mt][0], a[mt][1], a[mt][2], a[mt][3], ba + aAddr[mt][ks]);
#pragma unroll
            for (int np = 0; np < 4; np++) {
                uint32_t b0, b1, b2, b3;
                ldsm_x4(b0, b1, b2, b3, bw + wAddr[np][ks]);
#pragma unroll
                for (int mt = 0; mt < 2; mt++) {
                    mma_h(c[mt][2*np][0], c[mt][2*np][1], c[mt][2*np][2], c[mt][2*np][3],
                          a[mt][0], a[mt][1], a[mt][2], a[mt][3], b0, b1);
                    mma_h(c[mt][2*np+1][0], c[mt][2*np+1][1], c[mt][2*np+1][2], c[mt][2*np+1][3],
                          a[mt][0], a[mt][1], a[mt][2], a[mt][3], b2, b3);
                }
            }
        }
        __syncthreads();
    }

    // epilogue
#pragma unroll
    for (int mt = 0; mt < 2; mt++) {
#pragma unroll
        for (int nt = 0; nt < 8; nt++) {
            int row = bm + rm*32 + mt*16 + g;
            int col = bn + wn + nt*8 + 2*t;
            float2 b2 = *(const float2*)(bias + col);
            float v0 = c[mt][nt][0] + b2.x, v1 = c[mt][nt][1] + b2.y;
            float v2 = c[mt][nt][2] + b2.x, v3 = c[mt][nt][3] + b2.y;
            if (mode == 0) {
                float* C = (float*)Cout;
                *(float2*)(C + (size_t)row * N + col) = make_float2(v0, v1);
                *(float2*)(C + (size_t)(row + 8) * N + col) = make_float2(v2, v3);
            } else if (mode == 3) {
                __half* C = (__half*)Cout;
                int b0r = row / S, s0 = row - b0r * S;
                size_t r0 = (size_t)(b0r * 768 + col) * S;
                C[r0 + s0] = __float2half(v0);
                C[r0 + S + s0] = __float2half(v1);
                C[r0 + s0 + 8] = __float2half(v2);
                C[r0 + S + s0 + 8] = __float2half(v3);
            } else {
                float sc = (mode == 1) ? SCALE_Q : 1.0f;
                __half* C = (__half*)Cout;
                *(uint32_t*)(C + (size_t)row * N + col) = packh2(v0 * sc, v1 * sc);
                *(uint32_t*)(C + (size_t)(row + 8) * N + col) = packh2(v2 * sc, v3 * sc);
            }
        }
    }
}

// ============================================================================
// fp16 flash attention, 16B cp.async + ldmatrix, per-mt softmax/PV fusion.
// 128 threads, warp owns 32 q-rows, CTA = 128 rows, KV tile 64 keys.
// smem: Q 16KB | K0 8KB | K1 8KB | V0 8KB | V1 8KB = 48KB
// ============================================================================
#define FQ_B  0
#define FK0_B 16384
#define FK1_B 24576
#define FV0_B 32768
#define FV1_B 40960

__global__ __launch_bounds__(128) void flash_h(
    const __half* __restrict__ Qg, const __half* __restrict__ Kg,
    const __half* __restrict__ Vtg, __half* __restrict__ Op, int S)
{
    __shared__ char smc[49152];
    const uint32_t smb = smem_u32(smc);

    const int tid  = threadIdx.x;
    const int lane = tid & 31, warp = tid >> 5;
    const int g = lane >> 2, t = lane & 3;
    const int b = blockIdx.y / NHEAD, h = blockIdx.y % NHEAD;
    const int q0 = blockIdx.x * 128;
    const __half* qbase = Qg + ((size_t)b * S) * D_MODEL + h * DK;
    const __half* kbase = Kg + ((size_t)b * S) * D_MODEL + h * DK;
    const __half* vbase = Vtg + (size_t)(b * 768 + h * 64) * S;

    uint32_t bAddr[4][4];
#pragma unroll
    for (int np = 0; np < 4; np++) {
        int row = np*16 + ((lane >> 4) & 1) * 8 + (lane & 7);
#pragma unroll
        for (int ks = 0; ks < 4; ks++) {
            int ch = ks*2 + ((lane >> 3) & 1);
            bAddr[np][ks] = (uint32_t)((row*8 + (ch ^ (row & 7))) * 16);
        }
    }

    // ---- stage Q as its own cp.async group ----
#pragma unroll
    for (int j = 0; j < 8; j++) {
        int fl = j * 128 + tid;
        int row = fl >> 3, ch = fl & 7;
        int phys = ch ^ (row & 7);
        cpasync16(smb + FQ_B + (uint32_t)(row*8 + phys)*16,
                  qbase + (size_t)(q0 + row) * D_MODEL + ch*8);
    }
    CP_COMMIT();
    // ---- prefetch KV tile 0 ----
#pragma unroll
    for (int j = 0; j < 4; j++) {
        int fl = j * 128 + tid;
        int row = fl >> 3, ch = fl & 7;
        int phys = ch ^ (row & 7);
        cpasync16(smb + FK0_B + (uint32_t)(row*8 + phys)*16,
                  kbase + (size_t)row * D_MODEL + ch*8);
        cpasync16(smb + FV0_B + (uint32_t)(row*8 + phys)*16,
                  vbase + (size_t)row * S + ch*8);
    }
    CP_COMMIT();
    CP_WAIT1();            // Q group done
    __syncthreads();

    // ---- hoist Q fragments to registers (once) ----
    uint32_t qa[2][4][4];
#pragma unroll
    for (int mt = 0; mt < 2; mt++) {
        int row = warp*32 + mt*16 + (lane & 15);
#pragma unroll
        for (int ks = 0; ks < 4; ks++) {
            int ch = ks*2 + (lane >> 4);
            uint32_t addr = smb + FQ_B + (uint32_t)((row*8 + (ch ^ (row & 7)))*16);
            ldsm_x4(qa[mt][ks][0], qa[mt][ks][1], qa[mt][ks][2], qa[mt][ks][3], addr);
        }
    }

    float o[2][8][4] = {};
    float m_[2][2], l_[2][2];
#pragma unroll
    for (int mt = 0; mt < 2; mt++) {
        m_[mt][0] = m_[mt][1] = -CUDART_INF_F;
        l_[mt][0] = l_[mt][1] = 0.f;
    }

    const int niter = S / 64;
    for (int i = 0; i < niter; i++) {
        if (i + 1 < niter) {
            uint32_t fk = ((i + 1) & 1) ? FK1_B : FK0_B;
            uint32_t fv = ((i + 1) & 1) ? FV1_B : FV0_B;
            const __half* kg = kbase + (size_t)(i + 1) * 64 * D_MODEL;
            const __half* vg = vbase + (size_t)(i + 1) * 64;
#pragma unroll
            for (int j = 0; j < 4; j++) {
                int fl = j * 128 + tid;
                int row = fl >> 3, ch = fl & 7;
                int phys = ch ^ (row & 7);
                cpasync16(smb + fk + (uint32_t)(row*8 + phys)*16,
                          kg + (size_t)row * D_MODEL + ch*8);
                cpasync16(smb + fv + (uint32_t)(row*8 + phys)*16,
                          vg + (size_t)row * S + ch*8);
            }
        }
        CP_COMMIT();
        CP_WAIT1();
        __syncthreads();

        const uint32_t fk = smb + ((i & 1) ? FK1_B : FK0_B);
        const uint32_t fv = smb + ((i & 1) ? FV1_B : FV0_B);

        // ---- S = Q @ K^T ----
        float s[2][8][4] = {};
#pragma unroll
        for (int ks = 0; ks < 4; ks++) {
#pragma unroll
            for (int np = 0; np < 4; np++) {
                uint32_t b0, b1, b2, b3;
                ldsm_x4(b0, b1, b2, b3, fk + bAddr[np][ks]);
#pragma unroll
                for (int mt = 0; mt < 2; mt++) {
                    mma_h(s[mt][2*np][0], s[mt][2*np][1], s[mt][2*np][2], s[mt][2*np][3],
                          qa[mt][ks][0], qa[mt][ks][1], qa[mt][ks][2], qa[mt][ks][3], b0, b1);
                    mma_h(s[mt][2*np+1][0], s[mt][2*np+1][1], s[mt][2*np+1][2], s[mt][2*np+1][3],
                          qa[mt][ks][0], qa[mt][ks][1], qa[mt][ks][2], qa[mt][ks][3], b2, b3);
                }
            }
        }

        // ---- per-mt: softmax then PV (PV(mt0) overlaps softmax(mt1)) ----
#pragma unroll
        for (int mt = 0; mt < 2; mt++) {
            float mx0 = -CUDART_INF_F, mx1 = -CUDART_INF_F;
#pragma unroll
            for (int nt = 0; nt < 8; nt++) {
                mx0 = fmaxf(mx0, fmaxf(s[mt][nt][0], s[mt][nt][1]));
                mx1 = fmaxf(mx1, fmaxf(s[mt][nt][2], s[mt][nt][3]));
            }
#pragma unroll
            for (int off = 2; off >= 1; off >>= 1) {
                mx0 = fmaxf(mx0, __shfl_xor_sync(0xffffffffu, mx0, off));
                mx1 = fmaxf(mx1, __shfl_xor_sync(0xffffffffu, mx1, off));
            }
            float mn0 = fmaxf(m_[mt][0], mx0), mn1 = fmaxf(m_[mt][1], mx1);
            float al0 = exp2f(m_[mt][0] - mn0), al1 = exp2f(m_[mt][1] - mn1);
            m_[mt][0] = mn0; m_[mt][1] = mn1;

            uint32_t pp[8][2];
            float rs0 = 0.f, rs1 = 0.f;
#pragma unroll
            for (int nt = 0; nt < 8; nt++) {
                float p0 = exp2f(s[mt][nt][0] - mn0);
                float p1 = exp2f(s[mt][nt][1] - mn0);
                float p2 = exp2f(s[mt][nt][2] - mn1);
                float p3 = exp2f(s[mt][nt][3] - mn1);
                rs0 += p0 + p1; rs1 += p2 + p3;
                pp[nt][0] = packh2(p0, p1);
                pp[nt][1] = packh2(p2, p3);
            }
#pragma unroll
            for (int off = 2; off >= 1; off >>= 1) {
                rs0 += __shfl_xor_sync(0xffffffffu, rs0, off);
                rs1 += __shfl_xor_sync(0xffffffffu, rs1, off);
            }
            l_[mt][0] = l_[mt][0] * al0 + rs0;
            l_[mt][1] = l_[mt][1] * al1 + rs1;
#pragma unroll
            for (int nt = 0; nt < 8; nt++) {
                o[mt][nt][0] *= al0; o[mt][nt][1] *= al0;
                o[mt][nt][2] *= al1; o[mt][nt][3] *= al1;
            }

            // PV for this mt (V ldsm per mt; overlaps next mt's softmax)
#pragma unroll
            for (int ks = 0; ks < 4; ks++) {
#pragma unroll
                for (int np = 0; np < 4; np++) {
                    uint32_t b0, b1, b2, b3;
                    ldsm_x4(b0, b1, b2, b3, fv + bAddr[np][ks]);
                    mma_h(o[mt][2*np][0], o[mt][2*np][1], o[mt][2*np][2], o[mt][2*np][3],
                          pp[2*ks][0], pp[2*ks][1], pp[2*ks+1][0], pp[2*ks+1][1], b0, b1);
                    mma_h(o[mt][2*np+1][0], o[mt][2*np+1][1], o[mt][2*np+1][2], o[mt][2*np+1][3],
                          pp[2*ks][0], pp[2*ks][1], pp[2*ks+1][0], pp[2*ks+1][1], b2, b3);
                }
            }
        }
        __syncthreads();
    }

    // ---- epilogue: normalize, write fp16 (B,S,768) ----
    __half* obase = Op + ((size_t)b * S) * D_MODEL + h * DK;
#pragma unroll
    for (int mt = 0; mt < 2; mt++) {
        float inv0 = 1.f / l_[mt][0], inv1 = 1.f / l_[mt][1];
        int row = q0 + 32*warp + 16*mt + g;
#pragma unroll
        for (int nt = 0; nt < 8; nt++) {
            int col = nt*8 + 2*t;
            *(uint32_t*)(obase + (size_t)row * D_MODEL + col) =
                packh2(o[mt][nt][0]*inv0, o[mt][nt][1]*inv0);
            *(uint32_t*)(obase + (size_t)(row + 8) * D_MODEL + col) =
                packh2(o[mt][nt][2]*inv1, o[mt][nt][3]*inv1);
        }
    }
}

// ============================================================================
extern "C" void kernel_launch(void* const* d_in, const int* in_sizes, int n_in,
                              void* d_out, int out_size)
{
    const float* Q  = (const float*)d_in[0];
    const float* K  = (const float*)d_in[1];
    const float* V  = (const float*)d_in[2];
    const float* Wq = (const float*)d_in[3];
    const float* bq = (const float*)d_in[4];
    const float* Wk = (const float*)d_in[5];
    const float* bk = (const float*)d_in[6];
    const float* Wv = (const float*)d_in[7];
    const float* bv = (const float*)d_in[8];
    const float* Wo = (const float*)d_in[9];
    const float* bo = (const float*)d_in[10];
    float* out = (float*)d_out;

    const int M = in_sizes[0] / D_MODEL;   // B*S
    const int S = 4096;
    const int B = M / S;

    __half *xq, *xk, *xv, *wq, *wk, *wv, *wo, *qh, *kh, *vt, *aoh;
    cudaGetSymbolAddress((void**)&xq,  g_xq);
    cudaGetSymbolAddress((void**)&xk,  g_xk);
    cudaGetSymbolAddress((void**)&xv,  g_xv);
    cudaGetSymbolAddress((void**)&wq,  g_wq);
    cudaGetSymbolAddress((void**)&wk,  g_wk);
    cudaGetSymbolAddress((void**)&wv,  g_wv);
    cudaGetSymbolAddress((void**)&wo,  g_wo);
    cudaGetSymbolAddress((void**)&qh,  g_qh);
    cudaGetSymbolAddress((void**)&kh,  g_kh);
    cudaGetSymbolAddress((void**)&vt,  g_vt);
    cudaGetSymbolAddress((void**)&aoh, g_aoh);

    cudaFuncSetAttribute(gemm_h, cudaFuncAttributeMaxDynamicSharedMemorySize, GEMM_SMEM);

    const int nIn4 = (M * D_MODEL) / 4;
    const int nW4  = (D_MODEL * D_MODEL) / 4;
    cvt_multi<<<dim3(296, 3), 256>>>((const float4*)Q, (const float4*)K,
                                     (const float4*)V, (const float4*)V,
                                     (uint2*)xq, (uint2*)xk, (uint2*)xv, (uint2*)xv, nIn4);
    cvt_multi<<<dim3(296, 4), 256>>>((const float4*)Wq, (const float4*)Wk,
                                     (const float4*)Wv, (const float4*)Wo,
                                     (uint2*)wq, (uint2*)wk, (uint2*)wv, (uint2*)wo, nW4);

    dim3 tb(256);
    dim3 gg(D_MODEL / 128, M / 128);
    gemm_h<<<gg, tb, GEMM_SMEM>>>(xq, wq, bq, qh,  M, D_MODEL, D_MODEL, 1, S);
    gemm_h<<<gg, tb, GEMM_SMEM>>>(xk, wk, bk, kh,  M, D_MODEL, D_MODEL, 2, S);
    gemm_h<<<gg, tb, GEMM_SMEM>>>(xv, wv, bv, vt,  M, D_MODEL, D_MODEL, 3, S);

    flash_h<<<dim3(S / 128, B * NHEAD), dim3(128)>>>(qh, kh, vt, aoh, S);

    gemm_h<<<gg, tb, GEMM_SMEM>>>(aoh, wo, bo, out, M, D_MODEL, D_MODEL, 0, S);
}